// round 1
// baseline (speedup 1.0000x reference)
#include <cuda_runtime.h>
#include <cuda_bf16.h>
#include <math.h>

#define Bb 2
#define Nn 2048
#define Cc 768
#define Hh 12
#define Dh 64
#define Mrows (Bb * Nn)   // 4096

// Scratch (no cudaMalloc allowed)
__device__ float g_qkv[(size_t)Bb * Nn * 3 * Cc];   // [B,N,3,H,Dh]
__device__ float g_attn[(size_t)Bb * Nn * Cc];      // [B,N,C]

// ---------------------------------------------------------------------------
// Generic tiled fp32 GEMM with bias: C[M,N] = A[M,K] @ B[K,N] + bias[N]
// BM=BN=64, BK=16, 256 threads (16x16), 4x4 frags.
// ---------------------------------------------------------------------------
__global__ __launch_bounds__(256) void gemm_bias_kernel(
    const float* __restrict__ A, const float* __restrict__ B,
    const float* __restrict__ bias, float* __restrict__ C,
    int M, int N, int K)
{
    __shared__ float As[16][64];   // [k][m] (transposed)
    __shared__ float Bs[16][64];   // [k][n]

    const int tid = threadIdx.x;
    const int tx = tid & 15;
    const int ty = tid >> 4;
    const int m0 = blockIdx.y * 64;
    const int n0 = blockIdx.x * 64;

    // loader indices
    const int ar = tid >> 2;          // 0..63 (A row within tile)
    const int ac = (tid & 3) * 4;     // 0,4,8,12 (k offset)
    const int br = tid >> 4;          // 0..15 (B row = k)
    const int bc = (tid & 15) * 4;    // 0..60 (n offset)

    float acc[4][4] = {};

    for (int kb = 0; kb < K; kb += 16) {
        float4 av = *(const float4*)&A[(size_t)(m0 + ar) * K + kb + ac];
        As[ac + 0][ar] = av.x;
        As[ac + 1][ar] = av.y;
        As[ac + 2][ar] = av.z;
        As[ac + 3][ar] = av.w;
        *(float4*)&Bs[br][bc] = *(const float4*)&B[(size_t)(kb + br) * N + n0 + bc];
        __syncthreads();
#pragma unroll
        for (int kk = 0; kk < 16; kk++) {
            float4 a4 = *(const float4*)&As[kk][ty * 4];
            float4 b4 = *(const float4*)&Bs[kk][tx * 4];
            float a[4] = {a4.x, a4.y, a4.z, a4.w};
            float b[4] = {b4.x, b4.y, b4.z, b4.w};
#pragma unroll
            for (int i = 0; i < 4; i++)
#pragma unroll
                for (int j = 0; j < 4; j++)
                    acc[i][j] = fmaf(a[i], b[j], acc[i][j]);
        }
        __syncthreads();
    }

    float4 bv = *(const float4*)&bias[n0 + tx * 4];
    float bb[4] = {bv.x, bv.y, bv.z, bv.w};
#pragma unroll
    for (int i = 0; i < 4; i++) {
        int m = m0 + ty * 4 + i;
        float4 o;
        o.x = acc[i][0] + bb[0];
        o.y = acc[i][1] + bb[1];
        o.z = acc[i][2] + bb[2];
        o.w = acc[i][3] + bb[3];
        *(float4*)&C[(size_t)m * N + n0 + tx * 4] = o;
    }
}

// ---------------------------------------------------------------------------
// Fused RMSNorm + RoPE for q and k, in-place on g_qkv. One warp per row.
// Row order: warp -> (b, n, s in {q,k}, h)
// ---------------------------------------------------------------------------
__global__ __launch_bounds__(256) void norm_rope_kernel(
    float* __restrict__ qkv, const float* __restrict__ cosT,
    const float* __restrict__ sinT, const float* __restrict__ qn_w,
    const float* __restrict__ kn_w)
{
    int warp = (blockIdx.x * blockDim.x + threadIdx.x) >> 5;
    int lane = threadIdx.x & 31;

    int h = warp % Hh;
    int t = warp / Hh;
    int s = t & 1;
    t >>= 1;
    int n = t % Nn;
    int b = t / Nn;

    size_t base = ((((size_t)(b * Nn + n)) * 3 + s) * Hh + h) * Dh;
    float t0 = qkv[base + 2 * lane];
    float t1 = qkv[base + 2 * lane + 1];

    float ss = t0 * t0 + t1 * t1;
#pragma unroll
    for (int o = 16; o; o >>= 1) ss += __shfl_xor_sync(0xffffffffu, ss, o);
    float inv = rsqrtf(ss * (1.0f / (float)Dh) + 1e-6f);

    const float* w = s ? kn_w : qn_w;
    float x0 = t0 * inv * w[2 * lane];
    float x1 = t1 * inv * w[2 * lane + 1];

    float c = cosT[(size_t)n * (Dh / 2) + lane];
    float sn = sinT[(size_t)n * (Dh / 2) + lane];

    qkv[base + 2 * lane]     = x0 * c - x1 * sn;
    qkv[base + 2 * lane + 1] = x0 * sn + x1 * c;
}

// ---------------------------------------------------------------------------
// Flash attention (fp32 SIMT). Block = (q-tile 64, head, batch). 256 threads.
// Smem: Qt[d][m] 16KB, KPt 16KB (K transposed [d][n], reused as P [n][m]),
//       Vs[n][d] 16KB, + row stats.
// ---------------------------------------------------------------------------
__global__ __launch_bounds__(256) void attn_kernel(
    const float* __restrict__ qkv, float* __restrict__ out)
{
    extern __shared__ float sm[];
    float* Qt = sm;                  // [64][64]  Qt[d*64+m]
    float* KPt = Qt + 64 * 64;       // [64][64]  Kt[d*64+n]  -> later Pt[n*64+m]
    float* Vs = KPt + 64 * 64;       // [64][64]  Vs[n*64+d]
    float* row_max = Vs + 64 * 64;   // [64]
    float* row_sum = row_max + 64;   // [64]
    float* row_alpha = row_sum + 64; // [64]

    const int qt = blockIdx.x;
    const int h = blockIdx.y;
    const int b = blockIdx.z;
    const int tid = threadIdx.x;
    const int tx = tid & 15;
    const int ty = tid >> 4;
    const float scale = 0.125f; // 64^-0.5

    // Load Q tile, transposed into Qt[d][m]
    {
        int r = tid >> 2;
        int c = (tid & 3) * 16;
        size_t base = ((((size_t)(b * Nn + qt * 64 + r)) * 3 + 0) * Hh + h) * Dh;
#pragma unroll
        for (int u = 0; u < 16; u += 4) {
            float4 v = *(const float4*)&qkv[base + c + u];
            Qt[(c + u + 0) * 64 + r] = v.x;
            Qt[(c + u + 1) * 64 + r] = v.y;
            Qt[(c + u + 2) * 64 + r] = v.z;
            Qt[(c + u + 3) * 64 + r] = v.w;
        }
    }
    if (tid < 64) { row_max[tid] = -INFINITY; row_sum[tid] = 0.0f; }

    float acc[4][4] = {};
    __syncthreads();

    for (int kt = 0; kt < Nn / 64; kt++) {
        // Load K (transposed) and V tiles
        {
            int r = tid >> 2;
            int c = (tid & 3) * 16;
            size_t kbase = ((((size_t)(b * Nn + kt * 64 + r)) * 3 + 1) * Hh + h) * Dh;
            size_t vbase = ((((size_t)(b * Nn + kt * 64 + r)) * 3 + 2) * Hh + h) * Dh;
#pragma unroll
            for (int u = 0; u < 16; u += 4) {
                float4 kv = *(const float4*)&qkv[kbase + c + u];
                KPt[(c + u + 0) * 64 + r] = kv.x;
                KPt[(c + u + 1) * 64 + r] = kv.y;
                KPt[(c + u + 2) * 64 + r] = kv.z;
                KPt[(c + u + 3) * 64 + r] = kv.w;
                *(float4*)&Vs[r * 64 + c + u] = *(const float4*)&qkv[vbase + c + u];
            }
        }
        __syncthreads();

        // S = scale * Q @ K^T   (4x4 frag per thread)
        float s[4][4] = {};
#pragma unroll
        for (int d = 0; d < 64; d++) {
            float4 a4 = *(const float4*)&Qt[d * 64 + ty * 4];
            float4 b4 = *(const float4*)&KPt[d * 64 + tx * 4];
            float a[4] = {a4.x, a4.y, a4.z, a4.w};
            float bq[4] = {b4.x, b4.y, b4.z, b4.w};
#pragma unroll
            for (int i = 0; i < 4; i++)
#pragma unroll
                for (int j = 0; j < 4; j++)
                    s[i][j] = fmaf(a[i], bq[j], s[i][j]);
        }

        float tmax[4];
#pragma unroll
        for (int i = 0; i < 4; i++) {
#pragma unroll
            for (int j = 0; j < 4; j++) s[i][j] *= scale;
            tmax[i] = fmaxf(fmaxf(s[i][0], s[i][1]), fmaxf(s[i][2], s[i][3]));
        }
#pragma unroll
        for (int o = 8; o; o >>= 1)
#pragma unroll
            for (int i = 0; i < 4; i++)
                tmax[i] = fmaxf(tmax[i], __shfl_xor_sync(0xffffffffu, tmax[i], o));

        if (tx == 0) {
#pragma unroll
            for (int i = 0; i < 4; i++) {
                int m = ty * 4 + i;
                float mo = row_max[m];
                float mn = fmaxf(mo, tmax[i]);
                float al = __expf(mo - mn);
                row_max[m] = mn;
                row_alpha[m] = al;
                row_sum[m] *= al;
            }
        }
        __syncthreads();

        // P = exp(S - max), write transposed Pt[n][m] (reusing KPt), sum rows
        float tsum[4] = {0.f, 0.f, 0.f, 0.f};
#pragma unroll
        for (int i = 0; i < 4; i++) {
            float mrow = row_max[ty * 4 + i];
#pragma unroll
            for (int j = 0; j < 4; j++) {
                float p = __expf(s[i][j] - mrow);
                tsum[i] += p;
                KPt[(tx * 4 + j) * 64 + ty * 4 + i] = p;
            }
        }
#pragma unroll
        for (int o = 8; o; o >>= 1)
#pragma unroll
            for (int i = 0; i < 4; i++)
                tsum[i] += __shfl_xor_sync(0xffffffffu, tsum[i], o);
        if (tx == 0) {
#pragma unroll
            for (int i = 0; i < 4; i++) row_sum[ty * 4 + i] += tsum[i];
        }

        // rescale running O
#pragma unroll
        for (int i = 0; i < 4; i++) {
            float al = row_alpha[ty * 4 + i];
#pragma unroll
            for (int j = 0; j < 4; j++) acc[i][j] *= al;
        }
        __syncthreads();

        // O += P @ V
#pragma unroll
        for (int n = 0; n < 64; n++) {
            float4 p4 = *(const float4*)&KPt[n * 64 + ty * 4];
            float4 v4 = *(const float4*)&Vs[n * 64 + tx * 4];
            float p[4] = {p4.x, p4.y, p4.z, p4.w};
            float v[4] = {v4.x, v4.y, v4.z, v4.w};
#pragma unroll
            for (int i = 0; i < 4; i++)
#pragma unroll
                for (int j = 0; j < 4; j++)
                    acc[i][j] = fmaf(p[i], v[j], acc[i][j]);
        }
        __syncthreads();
    }

    // Epilogue: divide by row sums, write to g_attn[b, n, h*64+d]
#pragma unroll
    for (int i = 0; i < 4; i++) {
        int m = qt * 64 + ty * 4 + i;
        float invl = 1.0f / row_sum[ty * 4 + i];
        float4 o;
        o.x = acc[i][0] * invl;
        o.y = acc[i][1] * invl;
        o.z = acc[i][2] * invl;
        o.w = acc[i][3] * invl;
        *(float4*)&out[((size_t)(b * Nn + m)) * Cc + h * 64 + tx * 4] = o;
    }
}

extern "C" void kernel_launch(void* const* d_in, const int* in_sizes, int n_in,
                              void* d_out, int out_size)
{
    const float* x      = (const float*)d_in[0];
    const float* cosT   = (const float*)d_in[1];
    const float* sinT   = (const float*)d_in[2];
    const float* qkv_w  = (const float*)d_in[3];
    const float* qkv_b  = (const float*)d_in[4];
    const float* proj_w = (const float*)d_in[5];
    const float* proj_b = (const float*)d_in[6];
    const float* qn_w   = (const float*)d_in[7];
    const float* kn_w   = (const float*)d_in[8];
    float* out = (float*)d_out;

    float* qkv = nullptr;
    float* attn = nullptr;
    cudaGetSymbolAddress((void**)&qkv, g_qkv);
    cudaGetSymbolAddress((void**)&attn, g_attn);

    // 1) QKV GEMM: [4096,768] @ [768,2304] + bias
    {
        dim3 grid((3 * Cc) / 64, Mrows / 64);
        gemm_bias_kernel<<<grid, 256>>>(x, qkv_w, qkv_b, qkv, Mrows, 3 * Cc, Cc);
    }

    // 2) RMSNorm + RoPE on q,k (in place)
    {
        int warps = Bb * Nn * 2 * Hh;          // 98304
        int blocks = warps / 8;                // 256 threads = 8 warps
        norm_rope_kernel<<<blocks, 256>>>(qkv, cosT, sinT, qn_w, kn_w);
    }

    // 3) Flash attention
    {
        int smem = (3 * 64 * 64 + 3 * 64) * (int)sizeof(float); // 49920 B
        cudaFuncSetAttribute(attn_kernel, cudaFuncAttributeMaxDynamicSharedMemorySize, smem);
        dim3 grid(Nn / 64, Hh, Bb);
        attn_kernel<<<grid, 256, smem>>>(qkv, attn);
    }

    // 4) Output projection: [4096,768] @ [768,768] + bias
    {
        dim3 grid(Cc / 64, Mrows / 64);
        gemm_bias_kernel<<<grid, 256>>>(attn, proj_w, proj_b, out, Mrows, Cc, Cc);
    }
}

// round 2
// speedup vs baseline: 1.0185x; 1.0185x over previous
#include <cuda_runtime.h>
#include <cuda_bf16.h>
#include <math.h>

#define Bb 2
#define Nn 2048
#define Cc 768
#define Hh 12
#define Dh 64
#define Mrows (Bb * Nn)   // 4096

// Scratch (no cudaMalloc allowed)
__device__ float g_qkv[(size_t)Bb * Nn * 3 * Cc];   // [B,N,3,H,Dh]
__device__ float g_attn[(size_t)Bb * Nn * Cc];      // [B,N,C]

// ---------------------------------------------------------------------------
// GEMM: C[M,N] = A[M,K] @ B[K,N] + bias[N]
// 128x128 tile, BK=16, 256 threads (16x16), 8x8 frags, double-buffered smem.
// ---------------------------------------------------------------------------
__global__ __launch_bounds__(256) void gemm128(
    const float* __restrict__ A, const float* __restrict__ B,
    const float* __restrict__ bias, float* __restrict__ C,
    int M, int N, int K)
{
    __shared__ float As[2][16][128];   // [buf][k][m]
    __shared__ float Bs[2][16][128];   // [buf][k][n]

    const int tid = threadIdx.x;
    const int tx = tid & 15;
    const int ty = tid >> 4;
    const int m0 = blockIdx.y * 128;
    const int n0 = blockIdx.x * 128;

    // loaders
    const int ar = tid >> 1;            // 0..127 (A row in tile)
    const int ak = (tid & 1) * 8;       // 0 or 8 (k offset)
    const int bk = tid >> 4;            // 0..15  (B k row)
    const int bn = (tid & 15) * 8;      // 0..120 (n offset)

    const float* Aptr = A + (size_t)(m0 + ar) * K + ak;
    const float* Bptr = B + (size_t)bk * N + n0 + bn;

    float4 pa0, pa1, pb0, pb1;

    // prologue: tile 0 -> buf 0
    pa0 = *(const float4*)(Aptr + 0);
    pa1 = *(const float4*)(Aptr + 4);
    pb0 = *(const float4*)(Bptr + 0);
    pb1 = *(const float4*)(Bptr + 4);
    As[0][ak + 0][ar] = pa0.x; As[0][ak + 1][ar] = pa0.y;
    As[0][ak + 2][ar] = pa0.z; As[0][ak + 3][ar] = pa0.w;
    As[0][ak + 4][ar] = pa1.x; As[0][ak + 5][ar] = pa1.y;
    As[0][ak + 6][ar] = pa1.z; As[0][ak + 7][ar] = pa1.w;
    *(float4*)&Bs[0][bk][bn]     = pb0;
    *(float4*)&Bs[0][bk][bn + 4] = pb1;
    __syncthreads();

    float acc[8][8] = {};
    const int NT = K / 16;

    for (int t = 0; t < NT; t++) {
        const int cb = t & 1;
        if (t + 1 < NT) {
            pa0 = *(const float4*)(Aptr + (size_t)(t + 1) * 16);
            pa1 = *(const float4*)(Aptr + (size_t)(t + 1) * 16 + 4);
            pb0 = *(const float4*)(Bptr + (size_t)(t + 1) * 16 * N);
            pb1 = *(const float4*)(Bptr + (size_t)(t + 1) * 16 * N + 4);
        }
#pragma unroll
        for (int kk = 0; kk < 16; kk++) {
            float4 a0 = *(const float4*)&As[cb][kk][ty * 4];
            float4 a1 = *(const float4*)&As[cb][kk][ty * 4 + 64];
            float4 b0 = *(const float4*)&Bs[cb][kk][tx * 4];
            float4 b1 = *(const float4*)&Bs[cb][kk][tx * 4 + 64];
            float a[8] = {a0.x, a0.y, a0.z, a0.w, a1.x, a1.y, a1.z, a1.w};
            float bb[8] = {b0.x, b0.y, b0.z, b0.w, b1.x, b1.y, b1.z, b1.w};
#pragma unroll
            for (int i = 0; i < 8; i++)
#pragma unroll
                for (int j = 0; j < 8; j++)
                    acc[i][j] = fmaf(a[i], bb[j], acc[i][j]);
        }
        if (t + 1 < NT) {
            const int nb = cb ^ 1;
            As[nb][ak + 0][ar] = pa0.x; As[nb][ak + 1][ar] = pa0.y;
            As[nb][ak + 2][ar] = pa0.z; As[nb][ak + 3][ar] = pa0.w;
            As[nb][ak + 4][ar] = pa1.x; As[nb][ak + 5][ar] = pa1.y;
            As[nb][ak + 6][ar] = pa1.z; As[nb][ak + 7][ar] = pa1.w;
            *(float4*)&Bs[nb][bk][bn]     = pb0;
            *(float4*)&Bs[nb][bk][bn + 4] = pb1;
            __syncthreads();
        }
    }

    // epilogue
    float4 bv0 = *(const float4*)&bias[n0 + tx * 4];
    float4 bv1 = *(const float4*)&bias[n0 + tx * 4 + 64];
    float bb0[4] = {bv0.x, bv0.y, bv0.z, bv0.w};
    float bb1[4] = {bv1.x, bv1.y, bv1.z, bv1.w};
#pragma unroll
    for (int i = 0; i < 8; i++) {
        int m = m0 + ty * 4 + (i < 4 ? i : 60 + i);
        float4 o0, o1;
        o0.x = acc[i][0] + bb0[0]; o0.y = acc[i][1] + bb0[1];
        o0.z = acc[i][2] + bb0[2]; o0.w = acc[i][3] + bb0[3];
        o1.x = acc[i][4] + bb1[0]; o1.y = acc[i][5] + bb1[1];
        o1.z = acc[i][6] + bb1[2]; o1.w = acc[i][7] + bb1[3];
        *(float4*)&C[(size_t)m * N + n0 + tx * 4]      = o0;
        *(float4*)&C[(size_t)m * N + n0 + tx * 4 + 64] = o1;
    }
}

// ---------------------------------------------------------------------------
// Fused RMSNorm + RoPE for q and k, in-place on g_qkv. One warp per row.
// ---------------------------------------------------------------------------
__global__ __launch_bounds__(256) void norm_rope_kernel(
    float* __restrict__ qkv, const float* __restrict__ cosT,
    const float* __restrict__ sinT, const float* __restrict__ qn_w,
    const float* __restrict__ kn_w)
{
    int warp = (blockIdx.x * blockDim.x + threadIdx.x) >> 5;
    int lane = threadIdx.x & 31;

    int h = warp % Hh;
    int t = warp / Hh;
    int s = t & 1;
    t >>= 1;
    int n = t % Nn;
    int b = t / Nn;

    size_t base = ((((size_t)(b * Nn + n)) * 3 + s) * Hh + h) * Dh;
    float t0 = qkv[base + 2 * lane];
    float t1 = qkv[base + 2 * lane + 1];

    float ss = t0 * t0 + t1 * t1;
#pragma unroll
    for (int o = 16; o; o >>= 1) ss += __shfl_xor_sync(0xffffffffu, ss, o);
    float inv = rsqrtf(ss * (1.0f / (float)Dh) + 1e-6f);

    const float* w = s ? kn_w : qn_w;
    float x0 = t0 * inv * w[2 * lane];
    float x1 = t1 * inv * w[2 * lane + 1];

    float c = cosT[(size_t)n * (Dh / 2) + lane];
    float sn = sinT[(size_t)n * (Dh / 2) + lane];

    qkv[base + 2 * lane]     = x0 * c - x1 * sn;
    qkv[base + 2 * lane + 1] = x0 * sn + x1 * c;
}

// ---------------------------------------------------------------------------
// Flash attention (fp32 SIMT). Q tile 128, K tile 128. 256 threads (16x16).
// S frag 8x8, O frag 8x4. P goes through smem transposed in two 64-key
// halves, reusing the K smem buffer. Padded strides kill bank conflicts.
// ---------------------------------------------------------------------------
#define QS 132   // padded row stride for Qt / KPt (floats)
#define VSd 68   // padded row stride for Vs (floats)

__global__ __launch_bounds__(256) void attn_kernel(
    const float* __restrict__ qkv, float* __restrict__ out)
{
    extern __shared__ float smf[];
    float* Qt  = smf;                    // [64][QS]  Qt[d][m]
    float* KPt = Qt + 64 * QS;           // [64][QS]  Kt[d][n] then Pt[n][m]
    float* Vs  = KPt + 64 * QS;          // [128][VSd] Vs[n][d]
    float* row_max   = Vs + 128 * VSd;   // [128]
    float* row_sum   = row_max + 128;    // [128]
    float* row_alpha = row_sum + 128;    // [128]

    const int qt = blockIdx.x;
    const int h  = blockIdx.y;
    const int b  = blockIdx.z;
    const int tid = threadIdx.x;
    const int tx = tid & 15;
    const int ty = tid >> 4;
    const float scale = 0.125f;

    int rowi[8];
#pragma unroll
    for (int i = 0; i < 8; i++) rowi[i] = ty * 4 + (i < 4 ? i : 60 + i);

    // load Q tile transposed -> Qt[d][m]
    {
        int r  = tid >> 1;
        int c0 = (tid & 1) * 32;
        size_t base = ((((size_t)(b * Nn + qt * 128 + r)) * 3 + 0) * Hh + h) * (size_t)Dh + c0;
#pragma unroll
        for (int u = 0; u < 32; u += 4) {
            float4 v = *(const float4*)&qkv[base + u];
            Qt[(c0 + u + 0) * QS + r] = v.x;
            Qt[(c0 + u + 1) * QS + r] = v.y;
            Qt[(c0 + u + 2) * QS + r] = v.z;
            Qt[(c0 + u + 3) * QS + r] = v.w;
        }
    }
    if (tid < 128) { row_max[tid] = -INFINITY; row_sum[tid] = 0.0f; }

    float acc[8][4] = {};

    for (int kt = 0; kt < Nn / 128; kt++) {
        __syncthreads();   // A: prev-iter PV2 reads done (first iter: Q/stat init done)

        // load K (transposed) + V tiles
        {
            int r  = tid >> 1;
            int c0 = (tid & 1) * 32;
            size_t kb = ((((size_t)(b * Nn + kt * 128 + r)) * 3 + 1) * Hh + h) * (size_t)Dh + c0;
            size_t vb = ((((size_t)(b * Nn + kt * 128 + r)) * 3 + 2) * Hh + h) * (size_t)Dh + c0;
#pragma unroll
            for (int u = 0; u < 32; u += 4) {
                float4 kv = *(const float4*)&qkv[kb + u];
                KPt[(c0 + u + 0) * QS + r] = kv.x;
                KPt[(c0 + u + 1) * QS + r] = kv.y;
                KPt[(c0 + u + 2) * QS + r] = kv.z;
                KPt[(c0 + u + 3) * QS + r] = kv.w;
                *(float4*)&Vs[r * VSd + c0 + u] = *(const float4*)&qkv[vb + u];
            }
        }
        __syncthreads();   // B: tiles visible

        // S = scale * Q @ K^T
        float s[8][8] = {};
#pragma unroll 8
        for (int d = 0; d < 64; d++) {
            float4 a0 = *(const float4*)&Qt[d * QS + ty * 4];
            float4 a1 = *(const float4*)&Qt[d * QS + ty * 4 + 64];
            float4 b0 = *(const float4*)&KPt[d * QS + tx * 4];
            float4 b1 = *(const float4*)&KPt[d * QS + tx * 4 + 64];
            float a[8] = {a0.x, a0.y, a0.z, a0.w, a1.x, a1.y, a1.z, a1.w};
            float bq[8] = {b0.x, b0.y, b0.z, b0.w, b1.x, b1.y, b1.z, b1.w};
#pragma unroll
            for (int i = 0; i < 8; i++)
#pragma unroll
                for (int j = 0; j < 8; j++)
                    s[i][j] = fmaf(a[i], bq[j], s[i][j]);
        }

        // row max (over n) + online-softmax stat update
        float tmax[8];
#pragma unroll
        for (int i = 0; i < 8; i++) {
#pragma unroll
            for (int j = 0; j < 8; j++) s[i][j] *= scale;
            float m01 = fmaxf(fmaxf(s[i][0], s[i][1]), fmaxf(s[i][2], s[i][3]));
            float m23 = fmaxf(fmaxf(s[i][4], s[i][5]), fmaxf(s[i][6], s[i][7]));
            tmax[i] = fmaxf(m01, m23);
        }
#pragma unroll
        for (int o = 8; o; o >>= 1)
#pragma unroll
            for (int i = 0; i < 8; i++)
                tmax[i] = fmaxf(tmax[i], __shfl_xor_sync(0xffffffffu, tmax[i], o));

        if (tx == 0) {
#pragma unroll
            for (int i = 0; i < 8; i++) {
                int r = rowi[i];
                float mo = row_max[r];
                float mn = fmaxf(mo, tmax[i]);
                float al = __expf(mo - mn);
                row_max[r] = mn;
                row_alpha[r] = al;
                row_sum[r] *= al;
            }
        }
        __syncthreads();   // C: stats visible; all S reads of KPt complete

        // exp, row sums, rescale running O
        float tsum[8];
#pragma unroll
        for (int i = 0; i < 8; i++) {
            float mrow = row_max[rowi[i]];
            tsum[i] = 0.0f;
#pragma unroll
            for (int j = 0; j < 8; j++) {
                s[i][j] = __expf(s[i][j] - mrow);
                tsum[i] += s[i][j];
            }
        }
#pragma unroll
        for (int o = 8; o; o >>= 1)
#pragma unroll
            for (int i = 0; i < 8; i++)
                tsum[i] += __shfl_xor_sync(0xffffffffu, tsum[i], o);
        if (tx == 0) {
#pragma unroll
            for (int i = 0; i < 8; i++) row_sum[rowi[i]] += tsum[i];
        }
#pragma unroll
        for (int i = 0; i < 8; i++) {
            float al = row_alpha[rowi[i]];
#pragma unroll
            for (int j = 0; j < 4; j++) acc[i][j] *= al;
        }

        // store P half 1 transposed into KPt: n in [0,64)
#pragma unroll
        for (int i = 0; i < 8; i++) {
            int m = rowi[i];
#pragma unroll
            for (int jj = 0; jj < 4; jj++) {
                int j = (jj + tx) & 3;                 // skew to avoid bank conflicts
                KPt[(tx * 4 + j) * QS + m] = s[i][j];
            }
        }
        __syncthreads();   // D: Pt half1 visible

        // O += P1 @ V[0:64]
#pragma unroll 8
        for (int n = 0; n < 64; n++) {
            float4 p0 = *(const float4*)&KPt[n * QS + ty * 4];
            float4 p1 = *(const float4*)&KPt[n * QS + ty * 4 + 64];
            float4 v4 = *(const float4*)&Vs[n * VSd + tx * 4];
            float p[8] = {p0.x, p0.y, p0.z, p0.w, p1.x, p1.y, p1.z, p1.w};
            float v[4] = {v4.x, v4.y, v4.z, v4.w};
#pragma unroll
            for (int i = 0; i < 8; i++)
#pragma unroll
                for (int j = 0; j < 4; j++)
                    acc[i][j] = fmaf(p[i], v[j], acc[i][j]);
        }
        __syncthreads();   // E: PV1 reads done before overwrite

        // store P half 2 transposed into KPt: n in [64,128)
#pragma unroll
        for (int i = 0; i < 8; i++) {
            int m = rowi[i];
#pragma unroll
            for (int jj = 0; jj < 4; jj++) {
                int j = (jj + tx) & 3;
                KPt[(tx * 4 + j) * QS + m] = s[i][4 + j];
            }
        }
        __syncthreads();   // F: Pt half2 visible

        // O += P2 @ V[64:128]
#pragma unroll 8
        for (int n = 0; n < 64; n++) {
            float4 p0 = *(const float4*)&KPt[n * QS + ty * 4];
            float4 p1 = *(const float4*)&KPt[n * QS + ty * 4 + 64];
            float4 v4 = *(const float4*)&Vs[(64 + n) * VSd + tx * 4];
            float p[8] = {p0.x, p0.y, p0.z, p0.w, p1.x, p1.y, p1.z, p1.w};
            float v[4] = {v4.x, v4.y, v4.z, v4.w};
#pragma unroll
            for (int i = 0; i < 8; i++)
#pragma unroll
                for (int j = 0; j < 4; j++)
                    acc[i][j] = fmaf(p[i], v[j], acc[i][j]);
        }
    }

    // epilogue: normalize and write [b, n, h*64 + d]
#pragma unroll
    for (int i = 0; i < 8; i++) {
        int m = rowi[i];
        float inv = 1.0f / row_sum[m];
        float4 o;
        o.x = acc[i][0] * inv;
        o.y = acc[i][1] * inv;
        o.z = acc[i][2] * inv;
        o.w = acc[i][3] * inv;
        *(float4*)&out[((size_t)(b * Nn + qt * 128 + m)) * Cc + h * 64 + tx * 4] = o;
    }
}

extern "C" void kernel_launch(void* const* d_in, const int* in_sizes, int n_in,
                              void* d_out, int out_size)
{
    const float* x      = (const float*)d_in[0];
    const float* cosT   = (const float*)d_in[1];
    const float* sinT   = (const float*)d_in[2];
    const float* qkv_w  = (const float*)d_in[3];
    const float* qkv_b  = (const float*)d_in[4];
    const float* proj_w = (const float*)d_in[5];
    const float* proj_b = (const float*)d_in[6];
    const float* qn_w   = (const float*)d_in[7];
    const float* kn_w   = (const float*)d_in[8];
    float* out = (float*)d_out;

    float* qkv = nullptr;
    float* attn = nullptr;
    cudaGetSymbolAddress((void**)&qkv, g_qkv);
    cudaGetSymbolAddress((void**)&attn, g_attn);

    // 1) QKV GEMM: [4096,768] @ [768,2304] + bias
    {
        dim3 grid((3 * Cc) / 128, Mrows / 128);
        gemm128<<<grid, 256>>>(x, qkv_w, qkv_b, qkv, Mrows, 3 * Cc, Cc);
    }

    // 2) RMSNorm + RoPE on q,k (in place)
    {
        int warps = Bb * Nn * 2 * Hh;
        int blocks = warps / 8;
        norm_rope_kernel<<<blocks, 256>>>(qkv, cosT, sinT, qn_w, kn_w);
    }

    // 3) Flash attention
    {
        int smem = (2 * 64 * QS + 128 * VSd + 3 * 128) * (int)sizeof(float);
        cudaFuncSetAttribute(attn_kernel, cudaFuncAttributeMaxDynamicSharedMemorySize, smem);
        dim3 grid(Nn / 128, Hh, Bb);
        attn_kernel<<<grid, 256, smem>>>(qkv, attn);
    }

    // 4) Output projection: [4096,768] @ [768,768] + bias
    {
        dim3 grid(Cc / 128, Mrows / 128);
        gemm128<<<grid, 256>>>(attn, proj_w, proj_b, out, Mrows, Cc, Cc);
    }
}

// round 3
// speedup vs baseline: 1.1142x; 1.0939x over previous
#include <cuda_runtime.h>
#include <cuda_bf16.h>
#include <math.h>
#include <stdint.h>

#define Bb 2
#define Nn 2048
#define Cc 768
#define Hh 12
#define Dh 64
#define Mrows (Bb * Nn)   // 4096
#define K3 (3 * Cc)       // 2304 (split-expanded K)

// Scratch (no cudaMalloc allowed)
__device__ float g_qkv[(size_t)Bb * Nn * 3 * Cc];        // [B,N,3,H,Dh] f32
__device__ float g_attn[(size_t)Bb * Nn * Cc];           // [B,N,C] f32
__device__ __nv_bfloat16 g_xe[(size_t)Mrows * K3];       // x expanded (hi,lo,hi)
__device__ __nv_bfloat16 g_ae[(size_t)Mrows * K3];       // attn-out expanded
__device__ __nv_bfloat16 g_we1[(size_t)K3 * 3 * Cc];     // qkv_w expanded rows (hi,hi,lo)
__device__ __nv_bfloat16 g_we2[(size_t)K3 * Cc];         // proj_w expanded

// ---------------------------------------------------------------------------
// Fast exp (no MUFU): exp(x) for x <= 0 (handles -inf -> ~0). FMA/ALU only.
// ---------------------------------------------------------------------------
__device__ __forceinline__ float fexp(float x) {
    float t = x * 1.442695041f;
    t = fmaxf(t, -126.0f);
    float r = t + 12582912.0f;               // 1.5 * 2^23 : round-to-nearest
    int   ii = __float_as_int(r) - 0x4B400000;
    float f = t - (r - 12582912.0f);         // f in [-0.5, 0.5]
    float p = 1.3333558e-3f;                 // 2^f Taylor deg-5
    p = fmaf(p, f, 9.6181291e-3f);
    p = fmaf(p, f, 5.5504109e-2f);
    p = fmaf(p, f, 2.4022651e-1f);
    p = fmaf(p, f, 6.9314718e-1f);
    p = fmaf(p, f, 1.0f);
    return __int_as_float(__float_as_int(p) + (ii << 23));
}

// ---------------------------------------------------------------------------
// MMA / LDSM helpers
// ---------------------------------------------------------------------------
__device__ __forceinline__ void ldsm4(uint32_t& r0, uint32_t& r1, uint32_t& r2,
                                      uint32_t& r3, uint32_t addr) {
    asm volatile("ldmatrix.sync.aligned.m8n8.x4.shared.b16 {%0,%1,%2,%3}, [%4];"
                 : "=r"(r0), "=r"(r1), "=r"(r2), "=r"(r3) : "r"(addr));
}
__device__ __forceinline__ void ldsm4t(uint32_t& r0, uint32_t& r1, uint32_t& r2,
                                       uint32_t& r3, uint32_t addr) {
    asm volatile("ldmatrix.sync.aligned.m8n8.x4.trans.shared.b16 {%0,%1,%2,%3}, [%4];"
                 : "=r"(r0), "=r"(r1), "=r"(r2), "=r"(r3) : "r"(addr));
}
__device__ __forceinline__ void mma16816(float* c, uint32_t a0, uint32_t a1,
                                         uint32_t a2, uint32_t a3,
                                         uint32_t b0, uint32_t b1) {
    asm volatile(
        "mma.sync.aligned.m16n8k16.row.col.f32.bf16.bf16.f32 "
        "{%0,%1,%2,%3}, {%4,%5,%6,%7}, {%8,%9}, {%0,%1,%2,%3};"
        : "+f"(c[0]), "+f"(c[1]), "+f"(c[2]), "+f"(c[3])
        : "r"(a0), "r"(a1), "r"(a2), "r"(a3), "r"(b0), "r"(b1));
}

// ---------------------------------------------------------------------------
// Split-expansion kernels.
// Activations: X[M,K] f32 -> Xe[M,3K] bf16, per k: (hi, lo, hi)
// ---------------------------------------------------------------------------
__global__ __launch_bounds__(256) void expand_act(
    const float* __restrict__ X, __nv_bfloat16* __restrict__ Xe, int MK2, int K)
{
    int idx = blockIdx.x * 256 + threadIdx.x;
    if (idx >= MK2) return;
    int K2 = K >> 1;
    int m = idx / K2;
    int kk = idx - m * K2;
    float2 v = *(const float2*)(X + (size_t)m * K + 2 * kk);
    __nv_bfloat16 h0 = __float2bfloat16_rn(v.x);
    __nv_bfloat16 l0 = __float2bfloat16_rn(v.x - __bfloat162float(h0));
    __nv_bfloat16 h1 = __float2bfloat16_rn(v.y);
    __nv_bfloat16 l1 = __float2bfloat16_rn(v.y - __bfloat162float(h1));
    __nv_bfloat162* o2 = (__nv_bfloat162*)(Xe + (size_t)m * 3 * K + 6 * kk);
    o2[0] = __nv_bfloat162(h0, l0);
    o2[1] = __nv_bfloat162(h0, h1);
    o2[2] = __nv_bfloat162(l1, h1);
}

// Weights: W[K,N] f32 -> We[3K,N] bf16, rows per k: (hi, hi, lo)
__global__ __launch_bounds__(256) void expand_w(
    const float* __restrict__ W, __nv_bfloat16* __restrict__ We, int KN4, int N)
{
    int idx = blockIdx.x * 256 + threadIdx.x;
    if (idx >= KN4) return;
    int N4 = N >> 2;
    int k = idx / N4;
    int nn = (idx - k * N4) * 4;
    float4 w = *(const float4*)(W + (size_t)k * N + nn);
    __nv_bfloat16 hx = __float2bfloat16_rn(w.x), hy = __float2bfloat16_rn(w.y);
    __nv_bfloat16 hz = __float2bfloat16_rn(w.z), hw = __float2bfloat16_rn(w.w);
    __nv_bfloat16 lx = __float2bfloat16_rn(w.x - __bfloat162float(hx));
    __nv_bfloat16 ly = __float2bfloat16_rn(w.y - __bfloat162float(hy));
    __nv_bfloat16 lz = __float2bfloat16_rn(w.z - __bfloat162float(hz));
    __nv_bfloat16 lw = __float2bfloat16_rn(w.w - __bfloat162float(hw));
    __nv_bfloat162 hA(hx, hy), hB(hz, hw), lA(lx, ly), lB(lz, lw);
    size_t r = (size_t)(3 * k) * N + nn;
    *(__nv_bfloat162*)(We + r) = hA;            *(__nv_bfloat162*)(We + r + 2) = hB;
    r += N;
    *(__nv_bfloat162*)(We + r) = hA;            *(__nv_bfloat162*)(We + r + 2) = hB;
    r += N;
    *(__nv_bfloat162*)(We + r) = lA;            *(__nv_bfloat162*)(We + r + 2) = lB;
}

// ---------------------------------------------------------------------------
// bf16 tensor-core GEMM: C[M,N] = Ae[M,K3] @ Be[K3,N] + bias
// 128x128 tile, BK=48, 8 warps (2m x 4n), warp tile 64x32, double-buffered.
// ---------------------------------------------------------------------------
#define ASTR 56
#define BSTR 136
#define ASTG (128 * ASTR)
#define BSTG (48 * BSTR)

__global__ __launch_bounds__(256) void gemm_mma(
    const __nv_bfloat16* __restrict__ Ae, const __nv_bfloat16* __restrict__ Be,
    const float* __restrict__ bias, float* __restrict__ C,
    int M, int N, int Kt)
{
    extern __shared__ char gsm[];
    __nv_bfloat16* As = (__nv_bfloat16*)gsm;        // [2][128][ASTR]
    __nv_bfloat16* Bs = As + 2 * ASTG;              // [2][48][BSTR]

    const int tid = threadIdx.x;
    const int lane = tid & 31;
    const int wid = tid >> 5;
    const int wm = wid >> 2;          // 0..1
    const int wn = wid & 3;           // 0..3
    const int m0 = blockIdx.y * 128;
    const int n0 = blockIdx.x * 128;

    // loaders
    const int a_row = tid >> 1;               // 0..127
    const int a_col = (tid & 1) * 24;         // 0 / 24
    const int b_row0 = tid >> 4;              // 0..15
    const int b_col = (tid & 15) * 8;         // 0..120

    const __nv_bfloat16* Ag = Ae + (size_t)(m0 + a_row) * Kt + a_col;
    const __nv_bfloat16* Bg = Be + (size_t)b_row0 * N + n0 + b_col;

    const uint32_t as_u = (uint32_t)__cvta_generic_to_shared(As);
    const uint32_t bs_u = (uint32_t)__cvta_generic_to_shared(Bs);

    // ldmatrix lane addressing
    const int lrow = lane & 15;
    const int lsel = lane >> 4;               // 0/1 -> +8 cols

    uint4 ra[3], rb[3];
    // prologue: tile 0
#pragma unroll
    for (int u = 0; u < 3; u++) ra[u] = *(const uint4*)(Ag + u * 8);
#pragma unroll
    for (int p = 0; p < 3; p++) rb[p] = *(const uint4*)(Bg + (size_t)p * 16 * N);
#pragma unroll
    for (int u = 0; u < 3; u++)
        *(uint4*)&As[(size_t)a_row * ASTR + a_col + u * 8] = ra[u];
#pragma unroll
    for (int p = 0; p < 3; p++)
        *(uint4*)&Bs[(size_t)(b_row0 + p * 16) * BSTR + b_col] = rb[p];
    __syncthreads();

    float acc[4][4][4] = {};
    const int NT = Kt / 48;

    for (int kt = 0; kt < NT; kt++) {
        const int buf = kt & 1;
        if (kt + 1 < NT) {
            const __nv_bfloat16* Ag2 = Ag + (kt + 1) * 48;
            const __nv_bfloat16* Bg2 = Bg + (size_t)(kt + 1) * 48 * N;
#pragma unroll
            for (int u = 0; u < 3; u++) ra[u] = *(const uint4*)(Ag2 + u * 8);
#pragma unroll
            for (int p = 0; p < 3; p++) rb[p] = *(const uint4*)(Bg2 + (size_t)p * 16 * N);
        }

        const uint32_t aw = as_u + 2 * (buf * ASTG + (wm * 64 + lrow) * ASTR + lsel * 8);
        const uint32_t bw = bs_u + 2 * (buf * BSTG + lrow * BSTR + wn * 32 + lsel * 8);
#pragma unroll
        for (int ks = 0; ks < 3; ks++) {
            uint32_t af[4][4];
#pragma unroll
            for (int mf = 0; mf < 4; mf++)
                ldsm4(af[mf][0], af[mf][1], af[mf][2], af[mf][3],
                      aw + 2 * (mf * 16 * ASTR + ks * 16));
            uint32_t bf[2][4];
#pragma unroll
            for (int nc = 0; nc < 2; nc++)
                ldsm4t(bf[nc][0], bf[nc][1], bf[nc][2], bf[nc][3],
                       bw + 2 * (ks * 16 * BSTR + nc * 16));
#pragma unroll
            for (int mf = 0; mf < 4; mf++)
#pragma unroll
                for (int nf = 0; nf < 4; nf++)
                    mma16816(acc[mf][nf], af[mf][0], af[mf][1], af[mf][2], af[mf][3],
                             bf[nf >> 1][(nf & 1) * 2], bf[nf >> 1][(nf & 1) * 2 + 1]);
        }

        if (kt + 1 < NT) {
            const int nb = buf ^ 1;
#pragma unroll
            for (int u = 0; u < 3; u++)
                *(uint4*)&As[(size_t)(nb * ASTG + a_row * ASTR + a_col + u * 8)] = ra[u];
#pragma unroll
            for (int p = 0; p < 3; p++)
                *(uint4*)&Bs[(size_t)(nb * BSTG + (b_row0 + p * 16) * BSTR + b_col)] = rb[p];
            __syncthreads();
        }
    }

    // epilogue
#pragma unroll
    for (int nf = 0; nf < 4; nf++) {
        int n = n0 + wn * 32 + nf * 8 + (lane & 3) * 2;
        float2 bv = *(const float2*)&bias[n];
#pragma unroll
        for (int mf = 0; mf < 4; mf++) {
            int m = m0 + wm * 64 + mf * 16 + (lane >> 2);
            float2 o0 = {acc[mf][nf][0] + bv.x, acc[mf][nf][1] + bv.y};
            float2 o1 = {acc[mf][nf][2] + bv.x, acc[mf][nf][3] + bv.y};
            *(float2*)&C[(size_t)m * N + n]       = o0;
            *(float2*)&C[(size_t)(m + 8) * N + n] = o1;
        }
    }
}

// ---------------------------------------------------------------------------
// Fused RMSNorm + RoPE for q and k, in-place on g_qkv. One warp per row.
// ---------------------------------------------------------------------------
__global__ __launch_bounds__(256) void norm_rope_kernel(
    float* __restrict__ qkv, const float* __restrict__ cosT,
    const float* __restrict__ sinT, const float* __restrict__ qn_w,
    const float* __restrict__ kn_w)
{
    int warp = (blockIdx.x * blockDim.x + threadIdx.x) >> 5;
    int lane = threadIdx.x & 31;

    int h = warp % Hh;
    int t = warp / Hh;
    int s = t & 1;
    t >>= 1;
    int n = t % Nn;
    int b = t / Nn;

    size_t base = ((((size_t)(b * Nn + n)) * 3 + s) * Hh + h) * Dh;
    float t0 = qkv[base + 2 * lane];
    float t1 = qkv[base + 2 * lane + 1];

    float ss = t0 * t0 + t1 * t1;
#pragma unroll
    for (int o = 16; o; o >>= 1) ss += __shfl_xor_sync(0xffffffffu, ss, o);
    float inv = rsqrtf(ss * (1.0f / (float)Dh) + 1e-6f);

    const float* w = s ? kn_w : qn_w;
    float x0 = t0 * inv * w[2 * lane];
    float x1 = t1 * inv * w[2 * lane + 1];

    float c = cosT[(size_t)n * (Dh / 2) + lane];
    float sn = sinT[(size_t)n * (Dh / 2) + lane];

    qkv[base + 2 * lane]     = x0 * c - x1 * sn;
    qkv[base + 2 * lane + 1] = x0 * sn + x1 * c;
}

// ---------------------------------------------------------------------------
// Flash attention (fp32 SIMT, MUFU-free softmax). Q 128 x K 128 tiles.
// ---------------------------------------------------------------------------
#define QS 132
#define VSd 68

__global__ __launch_bounds__(256) void attn_kernel(
    const float* __restrict__ qkv, float* __restrict__ out)
{
    extern __shared__ float smf[];
    float* Qt  = smf;
    float* KPt = Qt + 64 * QS;
    float* Vs  = KPt + 64 * QS;
    float* row_max   = Vs + 128 * VSd;
    float* row_sum   = row_max + 128;
    float* row_alpha = row_sum + 128;

    const int qt = blockIdx.x;
    const int h  = blockIdx.y;
    const int b  = blockIdx.z;
    const int tid = threadIdx.x;
    const int tx = tid & 15;
    const int ty = tid >> 4;
    const float scale = 0.125f;

    int rowi[8];
#pragma unroll
    for (int i = 0; i < 8; i++) rowi[i] = ty * 4 + (i < 4 ? i : 60 + i);

    {
        int r  = tid >> 1;
        int c0 = (tid & 1) * 32;
        size_t base = ((((size_t)(b * Nn + qt * 128 + r)) * 3 + 0) * Hh + h) * (size_t)Dh + c0;
#pragma unroll
        for (int u = 0; u < 32; u += 4) {
            float4 v = *(const float4*)&qkv[base + u];
            Qt[(c0 + u + 0) * QS + r] = v.x;
            Qt[(c0 + u + 1) * QS + r] = v.y;
            Qt[(c0 + u + 2) * QS + r] = v.z;
            Qt[(c0 + u + 3) * QS + r] = v.w;
        }
    }
    if (tid < 128) { row_max[tid] = -INFINITY; row_sum[tid] = 0.0f; }

    float acc[8][4] = {};

    for (int kt = 0; kt < Nn / 128; kt++) {
        __syncthreads();

        {
            int r  = tid >> 1;
            int c0 = (tid & 1) * 32;
            size_t kb = ((((size_t)(b * Nn + kt * 128 + r)) * 3 + 1) * Hh + h) * (size_t)Dh + c0;
            size_t vb = ((((size_t)(b * Nn + kt * 128 + r)) * 3 + 2) * Hh + h) * (size_t)Dh + c0;
#pragma unroll
            for (int u = 0; u < 32; u += 4) {
                float4 kv = *(const float4*)&qkv[kb + u];
                KPt[(c0 + u + 0) * QS + r] = kv.x;
                KPt[(c0 + u + 1) * QS + r] = kv.y;
                KPt[(c0 + u + 2) * QS + r] = kv.z;
                KPt[(c0 + u + 3) * QS + r] = kv.w;
                *(float4*)&Vs[r * VSd + c0 + u] = *(const float4*)&qkv[vb + u];
            }
        }
        __syncthreads();

        float s[8][8] = {};
#pragma unroll 8
        for (int d = 0; d < 64; d++) {
            float4 a0 = *(const float4*)&Qt[d * QS + ty * 4];
            float4 a1 = *(const float4*)&Qt[d * QS + ty * 4 + 64];
            float4 b0 = *(const float4*)&KPt[d * QS + tx * 4];
            float4 b1 = *(const float4*)&KPt[d * QS + tx * 4 + 64];
            float a[8] = {a0.x, a0.y, a0.z, a0.w, a1.x, a1.y, a1.z, a1.w};
            float bq[8] = {b0.x, b0.y, b0.z, b0.w, b1.x, b1.y, b1.z, b1.w};
#pragma unroll
            for (int i = 0; i < 8; i++)
#pragma unroll
                for (int j = 0; j < 8; j++)
                    s[i][j] = fmaf(a[i], bq[j], s[i][j]);
        }

        float tmax[8];
#pragma unroll
        for (int i = 0; i < 8; i++) {
#pragma unroll
            for (int j = 0; j < 8; j++) s[i][j] *= scale;
            float m01 = fmaxf(fmaxf(s[i][0], s[i][1]), fmaxf(s[i][2], s[i][3]));
            float m23 = fmaxf(fmaxf(s[i][4], s[i][5]), fmaxf(s[i][6], s[i][7]));
            tmax[i] = fmaxf(m01, m23);
        }
#pragma unroll
        for (int o = 8; o; o >>= 1)
#pragma unroll
            for (int i = 0; i < 8; i++)
                tmax[i] = fmaxf(tmax[i], __shfl_xor_sync(0xffffffffu, tmax[i], o));

        if (tx == 0) {
#pragma unroll
            for (int i = 0; i < 8; i++) {
                int r = rowi[i];
                float mo = row_max[r];
                float mn = fmaxf(mo, tmax[i]);
                float al = fexp(mo - mn);
                row_max[r] = mn;
                row_alpha[r] = al;
                row_sum[r] *= al;
            }
        }
        __syncthreads();

        float tsum[8];
#pragma unroll
        for (int i = 0; i < 8; i++) {
            float mrow = row_max[rowi[i]];
            tsum[i] = 0.0f;
#pragma unroll
            for (int j = 0; j < 8; j++) {
                s[i][j] = fexp(s[i][j] - mrow);
                tsum[i] += s[i][j];
            }
        }
#pragma unroll
        for (int o = 8; o; o >>= 1)
#pragma unroll
            for (int i = 0; i < 8; i++)
                tsum[i] += __shfl_xor_sync(0xffffffffu, tsum[i], o);
        if (tx == 0) {
#pragma unroll
            for (int i = 0; i < 8; i++) row_sum[rowi[i]] += tsum[i];
        }
#pragma unroll
        for (int i = 0; i < 8; i++) {
            float al = row_alpha[rowi[i]];
#pragma unroll
            for (int j = 0; j < 4; j++) acc[i][j] *= al;
        }

#pragma unroll
        for (int i = 0; i < 8; i++) {
            int m = rowi[i];
#pragma unroll
            for (int jj = 0; jj < 4; jj++) {
                int j = (jj + tx) & 3;
                KPt[(tx * 4 + j) * QS + m] = s[i][j];
            }
        }
        __syncthreads();

#pragma unroll 8
        for (int n = 0; n < 64; n++) {
            float4 p0 = *(const float4*)&KPt[n * QS + ty * 4];
            float4 p1 = *(const float4*)&KPt[n * QS + ty * 4 + 64];
            float4 v4 = *(const float4*)&Vs[n * VSd + tx * 4];
            float p[8] = {p0.x, p0.y, p0.z, p0.w, p1.x, p1.y, p1.z, p1.w};
            float v[4] = {v4.x, v4.y, v4.z, v4.w};
#pragma unroll
            for (int i = 0; i < 8; i++)
#pragma unroll
                for (int j = 0; j < 4; j++)
                    acc[i][j] = fmaf(p[i], v[j], acc[i][j]);
        }
        __syncthreads();

#pragma unroll
        for (int i = 0; i < 8; i++) {
            int m = rowi[i];
#pragma unroll
            for (int jj = 0; jj < 4; jj++) {
                int j = (jj + tx) & 3;
                KPt[(tx * 4 + j) * QS + m] = s[i][4 + j];
            }
        }
        __syncthreads();

#pragma unroll 8
        for (int n = 0; n < 64; n++) {
            float4 p0 = *(const float4*)&KPt[n * QS + ty * 4];
            float4 p1 = *(const float4*)&KPt[n * QS + ty * 4 + 64];
            float4 v4 = *(const float4*)&Vs[(64 + n) * VSd + tx * 4];
            float p[8] = {p0.x, p0.y, p0.z, p0.w, p1.x, p1.y, p1.z, p1.w};
            float v[4] = {v4.x, v4.y, v4.z, v4.w};
#pragma unroll
            for (int i = 0; i < 8; i++)
#pragma unroll
                for (int j = 0; j < 4; j++)
                    acc[i][j] = fmaf(p[i], v[j], acc[i][j]);
        }
    }

#pragma unroll
    for (int i = 0; i < 8; i++) {
        int m = rowi[i];
        float inv = 1.0f / row_sum[m];
        float4 o;
        o.x = acc[i][0] * inv;
        o.y = acc[i][1] * inv;
        o.z = acc[i][2] * inv;
        o.w = acc[i][3] * inv;
        *(float4*)&out[((size_t)(b * Nn + qt * 128 + m)) * Cc + h * 64 + tx * 4] = o;
    }
}

extern "C" void kernel_launch(void* const* d_in, const int* in_sizes, int n_in,
                              void* d_out, int out_size)
{
    const float* x      = (const float*)d_in[0];
    const float* cosT   = (const float*)d_in[1];
    const float* sinT   = (const float*)d_in[2];
    const float* qkv_w  = (const float*)d_in[3];
    const float* qkv_b  = (const float*)d_in[4];
    const float* proj_w = (const float*)d_in[5];
    const float* proj_b = (const float*)d_in[6];
    const float* qn_w   = (const float*)d_in[7];
    const float* kn_w   = (const float*)d_in[8];
    float* out = (float*)d_out;

    float *qkv, *attn;
    __nv_bfloat16 *xe, *ae, *we1, *we2;
    cudaGetSymbolAddress((void**)&qkv, g_qkv);
    cudaGetSymbolAddress((void**)&attn, g_attn);
    cudaGetSymbolAddress((void**)&xe, g_xe);
    cudaGetSymbolAddress((void**)&ae, g_ae);
    cudaGetSymbolAddress((void**)&we1, g_we1);
    cudaGetSymbolAddress((void**)&we2, g_we2);

    const int gemm_smem = (2 * ASTG + 2 * BSTG) * 2;   // 54784 B
    cudaFuncSetAttribute(gemm_mma, cudaFuncAttributeMaxDynamicSharedMemorySize, gemm_smem);

    // 1) split-expand x and qkv_w
    {
        int n2 = Mrows * Cc / 2;
        expand_act<<<(n2 + 255) / 256, 256>>>(x, xe, n2, Cc);
        int n4 = Cc * (3 * Cc) / 4;
        expand_w<<<(n4 + 255) / 256, 256>>>(qkv_w, we1, n4, 3 * Cc);
    }

    // 2) QKV GEMM (bf16x3 tensor cores): [4096,2304] @ [2304,2304]
    {
        dim3 grid((3 * Cc) / 128, Mrows / 128);
        gemm_mma<<<grid, 256, gemm_smem>>>(xe, we1, qkv_b, qkv, Mrows, 3 * Cc, K3);
    }

    // 3) RMSNorm + RoPE on q,k (in place, f32)
    {
        int warps = Bb * Nn * 2 * Hh;
        norm_rope_kernel<<<warps / 8, 256>>>(qkv, cosT, sinT, qn_w, kn_w);
    }

    // 4) Flash attention (MUFU-free)
    {
        int smem = (2 * 64 * QS + 128 * VSd + 3 * 128) * (int)sizeof(float);
        cudaFuncSetAttribute(attn_kernel, cudaFuncAttributeMaxDynamicSharedMemorySize, smem);
        dim3 grid(Nn / 128, Hh, Bb);
        attn_kernel<<<grid, 256, smem>>>(qkv, attn);
    }

    // 5) expand attention output and proj_w, then proj GEMM
    {
        int n2 = Mrows * Cc / 2;
        expand_act<<<(n2 + 255) / 256, 256>>>(attn, ae, n2, Cc);
        int n4 = Cc * Cc / 4;
        expand_w<<<(n4 + 255) / 256, 256>>>(proj_w, we2, n4, Cc);
        dim3 grid(Cc / 128, Mrows / 128);
        gemm_mma<<<grid, 256, gemm_smem>>>(ae, we2, proj_b, out, Mrows, Cc, K3);
    }
}

// round 5
// speedup vs baseline: 1.3290x; 1.1928x over previous
#include <cuda_runtime.h>
#include <cuda_bf16.h>
#include <math.h>
#include <stdint.h>

#define Bb 2
#define Nn 2048
#define Cc 768
#define Hh 12
#define Dh 64
#define Mrows (Bb * Nn)   // 4096
#define K3 (3 * Cc)       // 2304 (split-expanded K)

// Scratch (no cudaMalloc allowed)
__device__ float g_qkv[(size_t)Bb * Nn * 3 * Cc];        // [B,N,3,H,Dh] f32
__device__ float g_attn[(size_t)Bb * Nn * Cc];           // [B,N,C] f32
__device__ __nv_bfloat16 g_xe[(size_t)Mrows * K3];       // x expanded (hi,lo,hi)
__device__ __nv_bfloat16 g_ae[(size_t)Mrows * K3];       // attn-out expanded
__device__ __nv_bfloat16 g_we1[(size_t)K3 * 3 * Cc];     // qkv_w expanded rows (hi,hi,lo)
__device__ __nv_bfloat16 g_we2[(size_t)K3 * Cc];         // proj_w expanded

// ---------------------------------------------------------------------------
// Fast exp (no MUFU): exp(x) for x <= 0. FMA/ALU only.
// ---------------------------------------------------------------------------
__device__ __forceinline__ float fexp(float x) {
    float t = x * 1.442695041f;
    t = fmaxf(t, -126.0f);
    float r = t + 12582912.0f;
    int   ii = __float_as_int(r) - 0x4B400000;
    float f = t - (r - 12582912.0f);
    float p = 1.3333558e-3f;
    p = fmaf(p, f, 9.6181291e-3f);
    p = fmaf(p, f, 5.5504109e-2f);
    p = fmaf(p, f, 2.4022651e-1f);
    p = fmaf(p, f, 6.9314718e-1f);
    p = fmaf(p, f, 1.0f);
    return __int_as_float(__float_as_int(p) + (ii << 23));
}

// ---------------------------------------------------------------------------
// Packed f32x2 helpers (FFMA2 path — only reachable via PTX)
// ---------------------------------------------------------------------------
typedef unsigned long long ull;
__device__ __forceinline__ ull dup2(float x) {
    ull r;
    asm("mov.b64 %0, {%1, %1};" : "=l"(r) : "f"(x));
    return r;
}
__device__ __forceinline__ void fma2(ull& d, ull a, ull b) {
    asm("fma.rn.f32x2 %0, %1, %2, %0;" : "+l"(d) : "l"(a), "l"(b));
}
__device__ __forceinline__ void mul2(ull& d, ull a) {
    asm("mul.rn.f32x2 %0, %0, %1;" : "+l"(d) : "l"(a));
}
__device__ __forceinline__ float2 unpk2(ull v) {
    float2 f;
    asm("mov.b64 {%0, %1}, %2;" : "=f"(f.x), "=f"(f.y) : "l"(v));
    return f;
}

// ---------------------------------------------------------------------------
// MMA / LDSM helpers
// ---------------------------------------------------------------------------
__device__ __forceinline__ void ldsm4(uint32_t& r0, uint32_t& r1, uint32_t& r2,
                                      uint32_t& r3, uint32_t addr) {
    asm volatile("ldmatrix.sync.aligned.m8n8.x4.shared.b16 {%0,%1,%2,%3}, [%4];"
                 : "=r"(r0), "=r"(r1), "=r"(r2), "=r"(r3) : "r"(addr));
}
__device__ __forceinline__ void ldsm4t(uint32_t& r0, uint32_t& r1, uint32_t& r2,
                                       uint32_t& r3, uint32_t addr) {
    asm volatile("ldmatrix.sync.aligned.m8n8.x4.trans.shared.b16 {%0,%1,%2,%3}, [%4];"
                 : "=r"(r0), "=r"(r1), "=r"(r2), "=r"(r3) : "r"(addr));
}
__device__ __forceinline__ void mma16816(float* c, uint32_t a0, uint32_t a1,
                                         uint32_t a2, uint32_t a3,
                                         uint32_t b0, uint32_t b1) {
    asm volatile(
        "mma.sync.aligned.m16n8k16.row.col.f32.bf16.bf16.f32 "
        "{%0,%1,%2,%3}, {%4,%5,%6,%7}, {%8,%9}, {%0,%1,%2,%3};"
        : "+f"(c[0]), "+f"(c[1]), "+f"(c[2]), "+f"(c[3])
        : "r"(a0), "r"(a1), "r"(a2), "r"(a3), "r"(b0), "r"(b1));
}

// ---------------------------------------------------------------------------
// Split-expansion kernels.
// ---------------------------------------------------------------------------
__global__ __launch_bounds__(256) void expand_act(
    const float* __restrict__ X, __nv_bfloat16* __restrict__ Xe, int MK2, int K)
{
    int idx = blockIdx.x * 256 + threadIdx.x;
    if (idx >= MK2) return;
    int K2 = K >> 1;
    int m = idx / K2;
    int kk = idx - m * K2;
    float2 v = *(const float2*)(X + (size_t)m * K + 2 * kk);
    __nv_bfloat16 h0 = __float2bfloat16_rn(v.x);
    __nv_bfloat16 l0 = __float2bfloat16_rn(v.x - __bfloat162float(h0));
    __nv_bfloat16 h1 = __float2bfloat16_rn(v.y);
    __nv_bfloat16 l1 = __float2bfloat16_rn(v.y - __bfloat162float(h1));
    __nv_bfloat162* o2 = (__nv_bfloat162*)(Xe + (size_t)m * 3 * K + 6 * kk);
    o2[0] = __nv_bfloat162(h0, l0);
    o2[1] = __nv_bfloat162(h0, h1);
    o2[2] = __nv_bfloat162(l1, h1);
}

__global__ __launch_bounds__(256) void expand_w(
    const float* __restrict__ W, __nv_bfloat16* __restrict__ We, int KN4, int N)
{
    int idx = blockIdx.x * 256 + threadIdx.x;
    if (idx >= KN4) return;
    int N4 = N >> 2;
    int k = idx / N4;
    int nn = (idx - k * N4) * 4;
    float4 w = *(const float4*)(W + (size_t)k * N + nn);
    __nv_bfloat16 hx = __float2bfloat16_rn(w.x), hy = __float2bfloat16_rn(w.y);
    __nv_bfloat16 hz = __float2bfloat16_rn(w.z), hw = __float2bfloat16_rn(w.w);
    __nv_bfloat16 lx = __float2bfloat16_rn(w.x - __bfloat162float(hx));
    __nv_bfloat16 ly = __float2bfloat16_rn(w.y - __bfloat162float(hy));
    __nv_bfloat16 lz = __float2bfloat16_rn(w.z - __bfloat162float(hz));
    __nv_bfloat16 lw = __float2bfloat16_rn(w.w - __bfloat162float(hw));
    __nv_bfloat162 hA(hx, hy), hB(hz, hw), lA(lx, ly), lB(lz, lw);
    size_t r = (size_t)(3 * k) * N + nn;
    *(__nv_bfloat162*)(We + r) = hA;            *(__nv_bfloat162*)(We + r + 2) = hB;
    r += N;
    *(__nv_bfloat162*)(We + r) = hA;            *(__nv_bfloat162*)(We + r + 2) = hB;
    r += N;
    *(__nv_bfloat162*)(We + r) = lA;            *(__nv_bfloat162*)(We + r + 2) = lB;
}

// ---------------------------------------------------------------------------
// bf16 tensor-core GEMM (mma.sync): C[M,N] = Ae[M,K3] @ Be[K3,N] + bias
// ---------------------------------------------------------------------------
#define ASTR 56
#define BSTR 136
#define ASTG (128 * ASTR)
#define BSTG (48 * BSTR)

__global__ __launch_bounds__(256) void gemm_mma(
    const __nv_bfloat16* __restrict__ Ae, const __nv_bfloat16* __restrict__ Be,
    const float* __restrict__ bias, float* __restrict__ C,
    int M, int N, int Kt)
{
    extern __shared__ char gsm[];
    __nv_bfloat16* As = (__nv_bfloat16*)gsm;
    __nv_bfloat16* Bs = As + 2 * ASTG;

    const int tid = threadIdx.x;
    const int lane = tid & 31;
    const int wid = tid >> 5;
    const int wm = wid >> 2;
    const int wn = wid & 3;
    const int m0 = blockIdx.y * 128;
    const int n0 = blockIdx.x * 128;

    const int a_row = tid >> 1;
    const int a_col = (tid & 1) * 24;
    const int b_row0 = tid >> 4;
    const int b_col = (tid & 15) * 8;

    const __nv_bfloat16* Ag = Ae + (size_t)(m0 + a_row) * Kt + a_col;
    const __nv_bfloat16* Bg = Be + (size_t)b_row0 * N + n0 + b_col;

    const uint32_t as_u = (uint32_t)__cvta_generic_to_shared(As);
    const uint32_t bs_u = (uint32_t)__cvta_generic_to_shared(Bs);

    const int lrow = lane & 15;
    const int lsel = lane >> 4;

    uint4 ra[3], rb[3];
#pragma unroll
    for (int u = 0; u < 3; u++) ra[u] = *(const uint4*)(Ag + u * 8);
#pragma unroll
    for (int p = 0; p < 3; p++) rb[p] = *(const uint4*)(Bg + (size_t)p * 16 * N);
#pragma unroll
    for (int u = 0; u < 3; u++)
        *(uint4*)&As[(size_t)a_row * ASTR + a_col + u * 8] = ra[u];
#pragma unroll
    for (int p = 0; p < 3; p++)
        *(uint4*)&Bs[(size_t)(b_row0 + p * 16) * BSTR + b_col] = rb[p];
    __syncthreads();

    float acc[4][4][4] = {};
    const int NT = Kt / 48;

    for (int kt = 0; kt < NT; kt++) {
        const int buf = kt & 1;
        if (kt + 1 < NT) {
            const __nv_bfloat16* Ag2 = Ag + (kt + 1) * 48;
            const __nv_bfloat16* Bg2 = Bg + (size_t)(kt + 1) * 48 * N;
#pragma unroll
            for (int u = 0; u < 3; u++) ra[u] = *(const uint4*)(Ag2 + u * 8);
#pragma unroll
            for (int p = 0; p < 3; p++) rb[p] = *(const uint4*)(Bg2 + (size_t)p * 16 * N);
        }

        const uint32_t aw = as_u + 2 * (buf * ASTG + (wm * 64 + lrow) * ASTR + lsel * 8);
        const uint32_t bw = bs_u + 2 * (buf * BSTG + lrow * BSTR + wn * 32 + lsel * 8);
#pragma unroll
        for (int ks = 0; ks < 3; ks++) {
            uint32_t af[4][4];
#pragma unroll
            for (int mf = 0; mf < 4; mf++)
                ldsm4(af[mf][0], af[mf][1], af[mf][2], af[mf][3],
                      aw + 2 * (mf * 16 * ASTR + ks * 16));
            uint32_t bf[2][4];
#pragma unroll
            for (int nc = 0; nc < 2; nc++)
                ldsm4t(bf[nc][0], bf[nc][1], bf[nc][2], bf[nc][3],
                       bw + 2 * (ks * 16 * BSTR + nc * 16));
#pragma unroll
            for (int mf = 0; mf < 4; mf++)
#pragma unroll
                for (int nf = 0; nf < 4; nf++)
                    mma16816(acc[mf][nf], af[mf][0], af[mf][1], af[mf][2], af[mf][3],
                             bf[nf >> 1][(nf & 1) * 2], bf[nf >> 1][(nf & 1) * 2 + 1]);
        }

        if (kt + 1 < NT) {
            const int nb = buf ^ 1;
#pragma unroll
            for (int u = 0; u < 3; u++)
                *(uint4*)&As[(size_t)(nb * ASTG + a_row * ASTR + a_col + u * 8)] = ra[u];
#pragma unroll
            for (int p = 0; p < 3; p++)
                *(uint4*)&Bs[(size_t)(nb * BSTG + (b_row0 + p * 16) * BSTR + b_col)] = rb[p];
            __syncthreads();
        }
    }

#pragma unroll
    for (int nf = 0; nf < 4; nf++) {
        int n = n0 + wn * 32 + nf * 8 + (lane & 3) * 2;
        float2 bv = *(const float2*)&bias[n];
#pragma unroll
        for (int mf = 0; mf < 4; mf++) {
            int m = m0 + wm * 64 + mf * 16 + (lane >> 2);
            float2 o0 = {acc[mf][nf][0] + bv.x, acc[mf][nf][1] + bv.y};
            float2 o1 = {acc[mf][nf][2] + bv.x, acc[mf][nf][3] + bv.y};
            *(float2*)&C[(size_t)m * N + n]       = o0;
            *(float2*)&C[(size_t)(m + 8) * N + n] = o1;
        }
    }
}

// ---------------------------------------------------------------------------
// Fused RMSNorm + RoPE for q and k, in-place on g_qkv. One warp per row.
// ---------------------------------------------------------------------------
__global__ __launch_bounds__(256) void norm_rope_kernel(
    float* __restrict__ qkv, const float* __restrict__ cosT,
    const float* __restrict__ sinT, const float* __restrict__ qn_w,
    const float* __restrict__ kn_w)
{
    int warp = (blockIdx.x * blockDim.x + threadIdx.x) >> 5;
    int lane = threadIdx.x & 31;

    int h = warp % Hh;
    int t = warp / Hh;
    int s = t & 1;
    t >>= 1;
    int n = t % Nn;
    int b = t / Nn;

    size_t base = ((((size_t)(b * Nn + n)) * 3 + s) * Hh + h) * Dh;
    float t0 = qkv[base + 2 * lane];
    float t1 = qkv[base + 2 * lane + 1];

    float ss = t0 * t0 + t1 * t1;
#pragma unroll
    for (int o = 16; o; o >>= 1) ss += __shfl_xor_sync(0xffffffffu, ss, o);
    float inv = rsqrtf(ss * (1.0f / (float)Dh) + 1e-6f);

    const float* w = s ? kn_w : qn_w;
    float x0 = t0 * inv * w[2 * lane];
    float x1 = t1 * inv * w[2 * lane + 1];

    float c = cosT[(size_t)n * (Dh / 2) + lane];
    float sn = sinT[(size_t)n * (Dh / 2) + lane];

    qkv[base + 2 * lane]     = x0 * c - x1 * sn;
    qkv[base + 2 * lane + 1] = x0 * sn + x1 * c;
}

// ---------------------------------------------------------------------------
// Flash attention (fp32 SIMT, FFMA2-packed inner GEMMs, MUFU-free softmax).
// Q tile 128 x K tile 128. 256 threads (16x16).
// ---------------------------------------------------------------------------
#define QS 132
#define VSd 68

__global__ __launch_bounds__(256) void attn_kernel(
    const float* __restrict__ qkv, float* __restrict__ out)
{
    extern __shared__ float smf[];
    float* Qt  = smf;
    float* KPt = Qt + 64 * QS;
    float* Vs  = KPt + 64 * QS;
    float* row_max   = Vs + 128 * VSd;
    float* row_sum   = row_max + 128;
    float* row_alpha = row_sum + 128;

    const int qt = blockIdx.x;
    const int h  = blockIdx.y;
    const int b  = blockIdx.z;
    const int tid = threadIdx.x;
    const int tx = tid & 15;
    const int ty = tid >> 4;
    const float scale = 0.125f;

    int rowi[8];
#pragma unroll
    for (int i = 0; i < 8; i++) rowi[i] = ty * 4 + (i < 4 ? i : 60 + i);

    {
        int r  = tid >> 1;
        int c0 = (tid & 1) * 32;
        size_t base = ((((size_t)(b * Nn + qt * 128 + r)) * 3 + 0) * Hh + h) * (size_t)Dh + c0;
#pragma unroll
        for (int u = 0; u < 32; u += 4) {
            float4 v = *(const float4*)&qkv[base + u];
            Qt[(c0 + u + 0) * QS + r] = v.x;
            Qt[(c0 + u + 1) * QS + r] = v.y;
            Qt[(c0 + u + 2) * QS + r] = v.z;
            Qt[(c0 + u + 3) * QS + r] = v.w;
        }
    }
    if (tid < 128) { row_max[tid] = -INFINITY; row_sum[tid] = 0.0f; }

    ull acc2[8][2] = {};   // packed O accumulator: [i][(j0,j1)|(j2,j3)]

    for (int kt = 0; kt < Nn / 128; kt++) {
        __syncthreads();

        {
            int r  = tid >> 1;
            int c0 = (tid & 1) * 32;
            size_t kb = ((((size_t)(b * Nn + kt * 128 + r)) * 3 + 1) * Hh + h) * (size_t)Dh + c0;
            size_t vb = ((((size_t)(b * Nn + kt * 128 + r)) * 3 + 2) * Hh + h) * (size_t)Dh + c0;
#pragma unroll
            for (int u = 0; u < 32; u += 4) {
                float4 kv = *(const float4*)&qkv[kb + u];
                KPt[(c0 + u + 0) * QS + r] = kv.x;
                KPt[(c0 + u + 1) * QS + r] = kv.y;
                KPt[(c0 + u + 2) * QS + r] = kv.z;
                KPt[(c0 + u + 3) * QS + r] = kv.w;
                *(float4*)&Vs[r * VSd + c0 + u] = *(const float4*)&qkv[vb + u];
            }
        }
        __syncthreads();

        // S = Q @ K^T, packed along j (key) pairs
        ull s2[8][4] = {};
#pragma unroll 4
        for (int d = 0; d < 64; d++) {
            float4 a0 = *(const float4*)&Qt[d * QS + ty * 4];
            float4 a1 = *(const float4*)&Qt[d * QS + ty * 4 + 64];
            ulonglong2 k0 = *(const ulonglong2*)&KPt[d * QS + tx * 4];
            ulonglong2 k1 = *(const ulonglong2*)&KPt[d * QS + tx * 4 + 64];
            ull ad[8] = {dup2(a0.x), dup2(a0.y), dup2(a0.z), dup2(a0.w),
                         dup2(a1.x), dup2(a1.y), dup2(a1.z), dup2(a1.w)};
            ull bj[4] = {k0.x, k0.y, k1.x, k1.y};
#pragma unroll
            for (int i = 0; i < 8; i++)
#pragma unroll
                for (int jp = 0; jp < 4; jp++)
                    fma2(s2[i][jp], ad[i], bj[jp]);
        }

        // unpack to scalars for softmax
        float s[8][8];
#pragma unroll
        for (int i = 0; i < 8; i++)
#pragma unroll
            for (int jp = 0; jp < 4; jp++) {
                float2 f = unpk2(s2[i][jp]);
                s[i][2 * jp]     = f.x;
                s[i][2 * jp + 1] = f.y;
            }

        float tmax[8];
#pragma unroll
        for (int i = 0; i < 8; i++) {
#pragma unroll
            for (int j = 0; j < 8; j++) s[i][j] *= scale;
            float m01 = fmaxf(fmaxf(s[i][0], s[i][1]), fmaxf(s[i][2], s[i][3]));
            float m23 = fmaxf(fmaxf(s[i][4], s[i][5]), fmaxf(s[i][6], s[i][7]));
            tmax[i] = fmaxf(m01, m23);
        }
#pragma unroll
        for (int o = 8; o; o >>= 1)
#pragma unroll
            for (int i = 0; i < 8; i++)
                tmax[i] = fmaxf(tmax[i], __shfl_xor_sync(0xffffffffu, tmax[i], o));

        if (tx == 0) {
#pragma unroll
            for (int i = 0; i < 8; i++) {
                int r = rowi[i];
                float mo = row_max[r];
                float mn = fmaxf(mo, tmax[i]);
                float al = fexp(mo - mn);
                row_max[r] = mn;
                row_alpha[r] = al;
                row_sum[r] *= al;
            }
        }
        __syncthreads();

        float tsum[8];
#pragma unroll
        for (int i = 0; i < 8; i++) {
            float mrow = row_max[rowi[i]];
            tsum[i] = 0.0f;
#pragma unroll
            for (int j = 0; j < 8; j++) {
                s[i][j] = fexp(s[i][j] - mrow);
                tsum[i] += s[i][j];
            }
        }
#pragma unroll
        for (int o = 8; o; o >>= 1)
#pragma unroll
            for (int i = 0; i < 8; i++)
                tsum[i] += __shfl_xor_sync(0xffffffffu, tsum[i], o);
        if (tx == 0) {
#pragma unroll
            for (int i = 0; i < 8; i++) row_sum[rowi[i]] += tsum[i];
        }
#pragma unroll
        for (int i = 0; i < 8; i++) {
            ull al = dup2(row_alpha[rowi[i]]);
            mul2(acc2[i][0], al);
            mul2(acc2[i][1], al);
        }

        // store P half 1 transposed into KPt: n in [0,64)
#pragma unroll
        for (int i = 0; i < 8; i++) {
            int m = rowi[i];
#pragma unroll
            for (int jj = 0; jj < 4; jj++) {
                int j = (jj + tx) & 3;
                KPt[(tx * 4 + j) * QS + m] = s[i][j];
            }
        }
        __syncthreads();

        // O += P1 @ V[0:64]  (packed along d pairs)
#pragma unroll 4
        for (int n = 0; n < 64; n++) {
            float4 p0 = *(const float4*)&KPt[n * QS + ty * 4];
            float4 p1 = *(const float4*)&KPt[n * QS + ty * 4 + 64];
            ulonglong2 vv = *(const ulonglong2*)&Vs[n * VSd + tx * 4];
            ull pd[8] = {dup2(p0.x), dup2(p0.y), dup2(p0.z), dup2(p0.w),
                         dup2(p1.x), dup2(p1.y), dup2(p1.z), dup2(p1.w)};
#pragma unroll
            for (int i = 0; i < 8; i++) {
                fma2(acc2[i][0], pd[i], vv.x);
                fma2(acc2[i][1], pd[i], vv.y);
            }
        }
        __syncthreads();

        // store P half 2 transposed into KPt: n in [64,128)
#pragma unroll
        for (int i = 0; i < 8; i++) {
            int m = rowi[i];
#pragma unroll
            for (int jj = 0; jj < 4; jj++) {
                int j = (jj + tx) & 3;
                KPt[(tx * 4 + j) * QS + m] = s[i][4 + j];
            }
        }
        __syncthreads();

        // O += P2 @ V[64:128]
#pragma unroll 4
        for (int n = 0; n < 64; n++) {
            float4 p0 = *(const float4*)&KPt[n * QS + ty * 4];
            float4 p1 = *(const float4*)&KPt[n * QS + ty * 4 + 64];
            ulonglong2 vv = *(const ulonglong2*)&Vs[(64 + n) * VSd + tx * 4];
            ull pd[8] = {dup2(p0.x), dup2(p0.y), dup2(p0.z), dup2(p0.w),
                         dup2(p1.x), dup2(p1.y), dup2(p1.z), dup2(p1.w)};
#pragma unroll
            for (int i = 0; i < 8; i++) {
                fma2(acc2[i][0], pd[i], vv.x);
                fma2(acc2[i][1], pd[i], vv.y);
            }
        }
    }

#pragma unroll
    for (int i = 0; i < 8; i++) {
        int m = rowi[i];
        float inv = 1.0f / row_sum[m];
        float2 f0 = unpk2(acc2[i][0]);
        float2 f1 = unpk2(acc2[i][1]);
        float4 o;
        o.x = f0.x * inv;
        o.y = f0.y * inv;
        o.z = f1.x * inv;
        o.w = f1.y * inv;
        *(float4*)&out[((size_t)(b * Nn + qt * 128 + m)) * Cc + h * 64 + tx * 4] = o;
    }
}

extern "C" void kernel_launch(void* const* d_in, const int* in_sizes, int n_in,
                              void* d_out, int out_size)
{
    const float* x      = (const float*)d_in[0];
    const float* cosT   = (const float*)d_in[1];
    const float* sinT   = (const float*)d_in[2];
    const float* qkv_w  = (const float*)d_in[3];
    const float* qkv_b  = (const float*)d_in[4];
    const float* proj_w = (const float*)d_in[5];
    const float* proj_b = (const float*)d_in[6];
    const float* qn_w   = (const float*)d_in[7];
    const float* kn_w   = (const float*)d_in[8];
    float* out = (float*)d_out;

    float *qkv, *attn;
    __nv_bfloat16 *xe, *ae, *we1, *we2;
    cudaGetSymbolAddress((void**)&qkv, g_qkv);
    cudaGetSymbolAddress((void**)&attn, g_attn);
    cudaGetSymbolAddress((void**)&xe, g_xe);
    cudaGetSymbolAddress((void**)&ae, g_ae);
    cudaGetSymbolAddress((void**)&we1, g_we1);
    cudaGetSymbolAddress((void**)&we2, g_we2);

    const int gemm_smem = (2 * ASTG + 2 * BSTG) * 2;   // 54784 B
    cudaFuncSetAttribute(gemm_mma, cudaFuncAttributeMaxDynamicSharedMemorySize, gemm_smem);

    // 1) split-expand x and qkv_w
    {
        int n2 = Mrows * Cc / 2;
        expand_act<<<(n2 + 255) / 256, 256>>>(x, xe, n2, Cc);
        int n4 = Cc * (3 * Cc) / 4;
        expand_w<<<(n4 + 255) / 256, 256>>>(qkv_w, we1, n4, 3 * Cc);
    }

    // 2) QKV GEMM (bf16x3 tensor cores): [4096,2304] @ [2304,2304]
    {
        dim3 grid((3 * Cc) / 128, Mrows / 128);
        gemm_mma<<<grid, 256, gemm_smem>>>(xe, we1, qkv_b, qkv, Mrows, 3 * Cc, K3);
    }

    // 3) RMSNorm + RoPE on q,k (in place, f32)
    {
        int warps = Bb * Nn * 2 * Hh;
        norm_rope_kernel<<<warps / 8, 256>>>(qkv, cosT, sinT, qn_w, kn_w);
    }

    // 4) Flash attention (FFMA2 + MUFU-free)
    {
        int smem = (2 * 64 * QS + 128 * VSd + 3 * 128) * (int)sizeof(float);
        cudaFuncSetAttribute(attn_kernel, cudaFuncAttributeMaxDynamicSharedMemorySize, smem);
        dim3 grid(Nn / 128, Hh, Bb);
        attn_kernel<<<grid, 256, smem>>>(qkv, attn);
    }

    // 5) expand attention output and proj_w, then proj GEMM
    {
        int n2 = Mrows * Cc / 2;
        expand_act<<<(n2 + 255) / 256, 256>>>(attn, ae, n2, Cc);
        int n4 = Cc * Cc / 4;
        expand_w<<<(n4 + 255) / 256, 256>>>(proj_w, we2, n4, Cc);
        dim3 grid(Cc / 128, Mrows / 128);
        gemm_mma<<<grid, 256, gemm_smem>>>(ae, we2, proj_b, out, Mrows, Cc, K3);
    }
}

// round 6
// speedup vs baseline: 1.3293x; 1.0002x over previous
#include <cuda_runtime.h>
#include <cuda_bf16.h>
#include <math.h>
#include <stdint.h>

#define Bb 2
#define Nn 2048
#define Cc 768
#define Hh 12
#define Dh 64
#define Mrows (Bb * Nn)   // 4096
#define K3 (3 * Cc)       // 2304 (split-expanded K)

// Scratch (no cudaMalloc allowed)
__device__ float g_qkv[(size_t)Bb * Nn * 3 * Cc];        // [B,N,3,H,Dh] f32
__device__ float g_attn[(size_t)Bb * Nn * Cc];           // [B,N,C] f32
__device__ __nv_bfloat16 g_xe[(size_t)Mrows * K3];       // x expanded (hi,lo,hi)
__device__ __nv_bfloat16 g_ae[(size_t)Mrows * K3];       // attn-out expanded
__device__ __nv_bfloat16 g_we1[(size_t)K3 * 3 * Cc];     // qkv_w expanded rows (hi,hi,lo)
__device__ __nv_bfloat16 g_we2[(size_t)K3 * Cc];         // proj_w expanded

// ---------------------------------------------------------------------------
// Fast exp (no MUFU): exp(x) for x <= 0. FMA/ALU only.
// ---------------------------------------------------------------------------
__device__ __forceinline__ float fexp(float x) {
    float t = x * 1.442695041f;
    t = fmaxf(t, -126.0f);
    float r = t + 12582912.0f;
    int   ii = __float_as_int(r) - 0x4B400000;
    float f = t - (r - 12582912.0f);
    float p = 1.3333558e-3f;
    p = fmaf(p, f, 9.6181291e-3f);
    p = fmaf(p, f, 5.5504109e-2f);
    p = fmaf(p, f, 2.4022651e-1f);
    p = fmaf(p, f, 6.9314718e-1f);
    p = fmaf(p, f, 1.0f);
    return __int_as_float(__float_as_int(p) + (ii << 23));
}

// ---------------------------------------------------------------------------
// Packed f32x2 helpers (FFMA2 path — only reachable via PTX)
// ---------------------------------------------------------------------------
typedef unsigned long long ull;
__device__ __forceinline__ ull dup2(float x) {
    ull r;
    asm("mov.b64 %0, {%1, %1};" : "=l"(r) : "f"(x));
    return r;
}
__device__ __forceinline__ void fma2(ull& d, ull a, ull b) {
    asm("fma.rn.f32x2 %0, %1, %2, %0;" : "+l"(d) : "l"(a), "l"(b));
}
__device__ __forceinline__ void mul2(ull& d, ull a) {
    asm("mul.rn.f32x2 %0, %0, %1;" : "+l"(d) : "l"(a));
}
__device__ __forceinline__ float2 unpk2(ull v) {
    float2 f;
    asm("mov.b64 {%0, %1}, %2;" : "=f"(f.x), "=f"(f.y) : "l"(v));
    return f;
}

// ---------------------------------------------------------------------------
// MMA / LDSM / cp.async helpers
// ---------------------------------------------------------------------------
__device__ __forceinline__ void ldsm4(uint32_t* r, uint32_t addr) {
    asm volatile("ldmatrix.sync.aligned.m8n8.x4.shared.b16 {%0,%1,%2,%3}, [%4];"
                 : "=r"(r[0]), "=r"(r[1]), "=r"(r[2]), "=r"(r[3]) : "r"(addr));
}
__device__ __forceinline__ void ldsm4t(uint32_t* r, uint32_t addr) {
    asm volatile("ldmatrix.sync.aligned.m8n8.x4.trans.shared.b16 {%0,%1,%2,%3}, [%4];"
                 : "=r"(r[0]), "=r"(r[1]), "=r"(r[2]), "=r"(r[3]) : "r"(addr));
}
__device__ __forceinline__ void mma16816(float* c, const uint32_t* a,
                                         uint32_t b0, uint32_t b1) {
    asm volatile(
        "mma.sync.aligned.m16n8k16.row.col.f32.bf16.bf16.f32 "
        "{%0,%1,%2,%3}, {%4,%5,%6,%7}, {%8,%9}, {%0,%1,%2,%3};"
        : "+f"(c[0]), "+f"(c[1]), "+f"(c[2]), "+f"(c[3])
        : "r"(a[0]), "r"(a[1]), "r"(a[2]), "r"(a[3]), "r"(b0), "r"(b1));
}
__device__ __forceinline__ void cpa16(uint32_t dst, const void* src) {
    asm volatile("cp.async.cg.shared.global [%0], [%1], 16;" :: "r"(dst), "l"(src));
}
#define CP_COMMIT() asm volatile("cp.async.commit_group;" ::: "memory")
#define CP_WAIT(n)  asm volatile("cp.async.wait_group %0;" :: "n"(n) : "memory")

// ---------------------------------------------------------------------------
// Split-expansion kernels.
// ---------------------------------------------------------------------------
__global__ __launch_bounds__(256) void expand_act(
    const float* __restrict__ X, __nv_bfloat16* __restrict__ Xe, int MK2, int K)
{
    int idx = blockIdx.x * 256 + threadIdx.x;
    if (idx >= MK2) return;
    int K2 = K >> 1;
    int m = idx / K2;
    int kk = idx - m * K2;
    float2 v = *(const float2*)(X + (size_t)m * K + 2 * kk);
    __nv_bfloat16 h0 = __float2bfloat16_rn(v.x);
    __nv_bfloat16 l0 = __float2bfloat16_rn(v.x - __bfloat162float(h0));
    __nv_bfloat16 h1 = __float2bfloat16_rn(v.y);
    __nv_bfloat16 l1 = __float2bfloat16_rn(v.y - __bfloat162float(h1));
    __nv_bfloat162* o2 = (__nv_bfloat162*)(Xe + (size_t)m * 3 * K + 6 * kk);
    o2[0] = __nv_bfloat162(h0, l0);
    o2[1] = __nv_bfloat162(h0, h1);
    o2[2] = __nv_bfloat162(l1, h1);
}

__global__ __launch_bounds__(256) void expand_w(
    const float* __restrict__ W, __nv_bfloat16* __restrict__ We, int KN4, int N)
{
    int idx = blockIdx.x * 256 + threadIdx.x;
    if (idx >= KN4) return;
    int N4 = N >> 2;
    int k = idx / N4;
    int nn = (idx - k * N4) * 4;
    float4 w = *(const float4*)(W + (size_t)k * N + nn);
    __nv_bfloat16 hx = __float2bfloat16_rn(w.x), hy = __float2bfloat16_rn(w.y);
    __nv_bfloat16 hz = __float2bfloat16_rn(w.z), hw = __float2bfloat16_rn(w.w);
    __nv_bfloat16 lx = __float2bfloat16_rn(w.x - __bfloat162float(hx));
    __nv_bfloat16 ly = __float2bfloat16_rn(w.y - __bfloat162float(hy));
    __nv_bfloat16 lz = __float2bfloat16_rn(w.z - __bfloat162float(hz));
    __nv_bfloat16 lw = __float2bfloat16_rn(w.w - __bfloat162float(hw));
    __nv_bfloat162 hA(hx, hy), hB(hz, hw), lA(lx, ly), lB(lz, lw);
    size_t r = (size_t)(3 * k) * N + nn;
    *(__nv_bfloat162*)(We + r) = hA;            *(__nv_bfloat162*)(We + r + 2) = hB;
    r += N;
    *(__nv_bfloat162*)(We + r) = hA;            *(__nv_bfloat162*)(We + r + 2) = hB;
    r += N;
    *(__nv_bfloat162*)(We + r) = lA;            *(__nv_bfloat162*)(We + r + 2) = lB;
}

// ---------------------------------------------------------------------------
// bf16 tensor-core GEMM (mma.sync): C[M,N] = Ae[M,K3] @ Be[K3,N] + bias
// CTA tile 256x128, BK=32, 8 warps (4m x 2n), warp tile 64x64,
// 3-stage cp.async pipeline.
// ---------------------------------------------------------------------------
#define PIPE 3
#define GAS 40                     // A smem row stride (elts)
#define GBS 136                    // B smem row stride (elts)
#define GA_SZ (256 * GAS)          // elts per stage
#define GB_SZ (32 * GBS)
#define STG_SZ (GA_SZ + GB_SZ)     // 14592 elts
#define GEMM_SMEM (PIPE * STG_SZ * 2)  // 87552 B

__global__ __launch_bounds__(256, 1) void gemm_mma(
    const __nv_bfloat16* __restrict__ Ae, const __nv_bfloat16* __restrict__ Be,
    const float* __restrict__ bias, float* __restrict__ C,
    int M, int N, int Kt)
{
    extern __shared__ __nv_bfloat16 gsm[];
    const int tid = threadIdx.x;
    const int lane = tid & 31;
    const int wid = tid >> 5;
    const int wm = wid >> 1;        // 0..3 (64 rows each)
    const int wn = wid & 1;         // 0..1 (64 cols each)
    const int m0 = blockIdx.y * 256;
    const int n0 = blockIdx.x * 128;

    const uint32_t smb = (uint32_t)__cvta_generic_to_shared(gsm);
    const int lrow = lane & 15;
    const int lsel = lane >> 4;

    // loader indices (A: 1024 16B chunks, B: 512 16B chunks)
    const int a_row = tid >> 2, a_u = tid & 3;          // +i*64 rows
    const int b_row = tid >> 4, b_u = tid & 15;         // +i*16 rows

    auto load_chunk = [&](int kt, int buf) {
        uint32_t sa = smb + buf * (STG_SZ * 2);
        const __nv_bfloat16* Agk = Ae + (size_t)m0 * Kt + kt * 32;
#pragma unroll
        for (int i = 0; i < 4; i++) {
            int row = a_row + i * 64;
            cpa16(sa + (row * GAS + a_u * 8) * 2,
                  Agk + (size_t)row * Kt + a_u * 8);
        }
        uint32_t sb = sa + GA_SZ * 2;
        const __nv_bfloat16* Bgk = Be + (size_t)(kt * 32) * N + n0;
#pragma unroll
        for (int i = 0; i < 2; i++) {
            int row = b_row + i * 16;
            cpa16(sb + (row * GBS + b_u * 8) * 2,
                  Bgk + (size_t)row * N + b_u * 8);
        }
    };

    const int NT = Kt / 32;

    // prologue: stages 0..PIPE-2
#pragma unroll
    for (int s = 0; s < PIPE - 1; s++) { load_chunk(s, s); CP_COMMIT(); }

    float acc[4][8][4] = {};

    for (int kt = 0; kt < NT; kt++) {
        CP_WAIT(PIPE - 2);
        __syncthreads();

        // issue load for chunk kt+PIPE-1 into the buffer freed at iter kt-1
        if (kt + PIPE - 1 < NT) {
            load_chunk(kt + PIPE - 1, (kt + PIPE - 1) % PIPE);
        }
        CP_COMMIT();   // keep group count in lockstep with iterations

        const int buf = kt % PIPE;
        const uint32_t aw = smb + buf * (STG_SZ * 2)
                          + 2 * ((wm * 64 + lrow) * GAS + lsel * 8);
        const uint32_t bw = smb + buf * (STG_SZ * 2) + GA_SZ * 2
                          + 2 * (lrow * GBS + wn * 64 + lsel * 8);
#pragma unroll
        for (int ks = 0; ks < 2; ks++) {
            uint32_t af[4][4];
#pragma unroll
            for (int mf = 0; mf < 4; mf++)
                ldsm4(af[mf], aw + 2 * (mf * 16 * GAS + ks * 16));
            uint32_t bfr[4][4];
#pragma unroll
            for (int nc = 0; nc < 4; nc++)
                ldsm4t(bfr[nc], bw + 2 * (ks * 16 * GBS + nc * 16));
#pragma unroll
            for (int mf = 0; mf < 4; mf++)
#pragma unroll
                for (int nf = 0; nf < 8; nf++)
                    mma16816(acc[mf][nf], af[mf],
                             bfr[nf >> 1][(nf & 1) * 2],
                             bfr[nf >> 1][(nf & 1) * 2 + 1]);
        }
        __syncthreads();
    }

    // epilogue
#pragma unroll
    for (int nf = 0; nf < 8; nf++) {
        int n = n0 + wn * 64 + nf * 8 + (lane & 3) * 2;
        float2 bv = *(const float2*)&bias[n];
#pragma unroll
        for (int mf = 0; mf < 4; mf++) {
            int m = m0 + wm * 64 + mf * 16 + (lane >> 2);
            float2 o0 = {acc[mf][nf][0] + bv.x, acc[mf][nf][1] + bv.y};
            float2 o1 = {acc[mf][nf][2] + bv.x, acc[mf][nf][3] + bv.y};
            *(float2*)&C[(size_t)m * N + n]       = o0;
            *(float2*)&C[(size_t)(m + 8) * N + n] = o1;
        }
    }
}

// ---------------------------------------------------------------------------
// Fused RMSNorm + RoPE for q and k, in-place on g_qkv. One warp per row.
// ---------------------------------------------------------------------------
__global__ __launch_bounds__(256) void norm_rope_kernel(
    float* __restrict__ qkv, const float* __restrict__ cosT,
    const float* __restrict__ sinT, const float* __restrict__ qn_w,
    const float* __restrict__ kn_w)
{
    int warp = (blockIdx.x * blockDim.x + threadIdx.x) >> 5;
    int lane = threadIdx.x & 31;

    int h = warp % Hh;
    int t = warp / Hh;
    int s = t & 1;
    t >>= 1;
    int n = t % Nn;
    int b = t / Nn;

    size_t base = ((((size_t)(b * Nn + n)) * 3 + s) * Hh + h) * Dh;
    float t0 = qkv[base + 2 * lane];
    float t1 = qkv[base + 2 * lane + 1];

    float ss = t0 * t0 + t1 * t1;
#pragma unroll
    for (int o = 16; o; o >>= 1) ss += __shfl_xor_sync(0xffffffffu, ss, o);
    float inv = rsqrtf(ss * (1.0f / (float)Dh) + 1e-6f);

    const float* w = s ? kn_w : qn_w;
    float x0 = t0 * inv * w[2 * lane];
    float x1 = t1 * inv * w[2 * lane + 1];

    float c = cosT[(size_t)n * (Dh / 2) + lane];
    float sn = sinT[(size_t)n * (Dh / 2) + lane];

    qkv[base + 2 * lane]     = x0 * c - x1 * sn;
    qkv[base + 2 * lane + 1] = x0 * sn + x1 * c;
}

// ---------------------------------------------------------------------------
// Flash attention (fp32 SIMT, FFMA2-packed inner GEMMs, MUFU-free softmax).
// ---------------------------------------------------------------------------
#define QS 132
#define VSd 68

__global__ __launch_bounds__(256) void attn_kernel(
    const float* __restrict__ qkv, float* __restrict__ out)
{
    extern __shared__ float smf[];
    float* Qt  = smf;
    float* KPt = Qt + 64 * QS;
    float* Vs  = KPt + 64 * QS;
    float* row_max   = Vs + 128 * VSd;
    float* row_sum   = row_max + 128;
    float* row_alpha = row_sum + 128;

    const int qt = blockIdx.x;
    const int h  = blockIdx.y;
    const int b  = blockIdx.z;
    const int tid = threadIdx.x;
    const int tx = tid & 15;
    const int ty = tid >> 4;
    const float scale = 0.125f;

    int rowi[8];
#pragma unroll
    for (int i = 0; i < 8; i++) rowi[i] = ty * 4 + (i < 4 ? i : 60 + i);

    {
        int r  = tid >> 1;
        int c0 = (tid & 1) * 32;
        size_t base = ((((size_t)(b * Nn + qt * 128 + r)) * 3 + 0) * Hh + h) * (size_t)Dh + c0;
#pragma unroll
        for (int u = 0; u < 32; u += 4) {
            float4 v = *(const float4*)&qkv[base + u];
            Qt[(c0 + u + 0) * QS + r] = v.x;
            Qt[(c0 + u + 1) * QS + r] = v.y;
            Qt[(c0 + u + 2) * QS + r] = v.z;
            Qt[(c0 + u + 3) * QS + r] = v.w;
        }
    }
    if (tid < 128) { row_max[tid] = -INFINITY; row_sum[tid] = 0.0f; }

    ull acc2[8][2] = {};

    for (int kt = 0; kt < Nn / 128; kt++) {
        __syncthreads();

        {
            int r  = tid >> 1;
            int c0 = (tid & 1) * 32;
            size_t kb = ((((size_t)(b * Nn + kt * 128 + r)) * 3 + 1) * Hh + h) * (size_t)Dh + c0;
            size_t vb = ((((size_t)(b * Nn + kt * 128 + r)) * 3 + 2) * Hh + h) * (size_t)Dh + c0;
#pragma unroll
            for (int u = 0; u < 32; u += 4) {
                float4 kv = *(const float4*)&qkv[kb + u];
                KPt[(c0 + u + 0) * QS + r] = kv.x;
                KPt[(c0 + u + 1) * QS + r] = kv.y;
                KPt[(c0 + u + 2) * QS + r] = kv.z;
                KPt[(c0 + u + 3) * QS + r] = kv.w;
                *(float4*)&Vs[r * VSd + c0 + u] = *(const float4*)&qkv[vb + u];
            }
        }
        __syncthreads();

        ull s2[8][4] = {};
#pragma unroll 4
        for (int d = 0; d < 64; d++) {
            float4 a0 = *(const float4*)&Qt[d * QS + ty * 4];
            float4 a1 = *(const float4*)&Qt[d * QS + ty * 4 + 64];
            ulonglong2 k0 = *(const ulonglong2*)&KPt[d * QS + tx * 4];
            ulonglong2 k1 = *(const ulonglong2*)&KPt[d * QS + tx * 4 + 64];
            ull ad[8] = {dup2(a0.x), dup2(a0.y), dup2(a0.z), dup2(a0.w),
                         dup2(a1.x), dup2(a1.y), dup2(a1.z), dup2(a1.w)};
            ull bj[4] = {k0.x, k0.y, k1.x, k1.y};
#pragma unroll
            for (int i = 0; i < 8; i++)
#pragma unroll
                for (int jp = 0; jp < 4; jp++)
                    fma2(s2[i][jp], ad[i], bj[jp]);
        }

        float s[8][8];
#pragma unroll
        for (int i = 0; i < 8; i++)
#pragma unroll
            for (int jp = 0; jp < 4; jp++) {
                float2 f = unpk2(s2[i][jp]);
                s[i][2 * jp]     = f.x;
                s[i][2 * jp + 1] = f.y;
            }

        float tmax[8];
#pragma unroll
        for (int i = 0; i < 8; i++) {
#pragma unroll
            for (int j = 0; j < 8; j++) s[i][j] *= scale;
            float m01 = fmaxf(fmaxf(s[i][0], s[i][1]), fmaxf(s[i][2], s[i][3]));
            float m23 = fmaxf(fmaxf(s[i][4], s[i][5]), fmaxf(s[i][6], s[i][7]));
            tmax[i] = fmaxf(m01, m23);
        }
#pragma unroll
        for (int o = 8; o; o >>= 1)
#pragma unroll
            for (int i = 0; i < 8; i++)
                tmax[i] = fmaxf(tmax[i], __shfl_xor_sync(0xffffffffu, tmax[i], o));

        if (tx == 0) {
#pragma unroll
            for (int i = 0; i < 8; i++) {
                int r = rowi[i];
                float mo = row_max[r];
                float mn = fmaxf(mo, tmax[i]);
                float al = fexp(mo - mn);
                row_max[r] = mn;
                row_alpha[r] = al;
                row_sum[r] *= al;
            }
        }
        __syncthreads();

        float tsum[8];
#pragma unroll
        for (int i = 0; i < 8; i++) {
            float mrow = row_max[rowi[i]];
            tsum[i] = 0.0f;
#pragma unroll
            for (int j = 0; j < 8; j++) {
                s[i][j] = fexp(s[i][j] - mrow);
                tsum[i] += s[i][j];
            }
        }
#pragma unroll
        for (int o = 8; o; o >>= 1)
#pragma unroll
            for (int i = 0; i < 8; i++)
                tsum[i] += __shfl_xor_sync(0xffffffffu, tsum[i], o);
        if (tx == 0) {
#pragma unroll
            for (int i = 0; i < 8; i++) row_sum[rowi[i]] += tsum[i];
        }
#pragma unroll
        for (int i = 0; i < 8; i++) {
            ull al = dup2(row_alpha[rowi[i]]);
            mul2(acc2[i][0], al);
            mul2(acc2[i][1], al);
        }

#pragma unroll
        for (int i = 0; i < 8; i++) {
            int m = rowi[i];
#pragma unroll
            for (int jj = 0; jj < 4; jj++) {
                int j = (jj + tx) & 3;
                KPt[(tx * 4 + j) * QS + m] = s[i][j];
            }
        }
        __syncthreads();

#pragma unroll 4
        for (int n = 0; n < 64; n++) {
            float4 p0 = *(const float4*)&KPt[n * QS + ty * 4];
            float4 p1 = *(const float4*)&KPt[n * QS + ty * 4 + 64];
            ulonglong2 vv = *(const ulonglong2*)&Vs[n * VSd + tx * 4];
            ull pd[8] = {dup2(p0.x), dup2(p0.y), dup2(p0.z), dup2(p0.w),
                         dup2(p1.x), dup2(p1.y), dup2(p1.z), dup2(p1.w)};
#pragma unroll
            for (int i = 0; i < 8; i++) {
                fma2(acc2[i][0], pd[i], vv.x);
                fma2(acc2[i][1], pd[i], vv.y);
            }
        }
        __syncthreads();

#pragma unroll
        for (int i = 0; i < 8; i++) {
            int m = rowi[i];
#pragma unroll
            for (int jj = 0; jj < 4; jj++) {
                int j = (jj + tx) & 3;
                KPt[(tx * 4 + j) * QS + m] = s[i][4 + j];
            }
        }
        __syncthreads();

#pragma unroll 4
        for (int n = 0; n < 64; n++) {
            float4 p0 = *(const float4*)&KPt[n * QS + ty * 4];
            float4 p1 = *(const float4*)&KPt[n * QS + ty * 4 + 64];
            ulonglong2 vv = *(const ulonglong2*)&Vs[(64 + n) * VSd + tx * 4];
            ull pd[8] = {dup2(p0.x), dup2(p0.y), dup2(p0.z), dup2(p0.w),
                         dup2(p1.x), dup2(p1.y), dup2(p1.z), dup2(p1.w)};
#pragma unroll
            for (int i = 0; i < 8; i++) {
                fma2(acc2[i][0], pd[i], vv.x);
                fma2(acc2[i][1], pd[i], vv.y);
            }
        }
    }

#pragma unroll
    for (int i = 0; i < 8; i++) {
        int m = rowi[i];
        float inv = 1.0f / row_sum[m];
        float2 f0 = unpk2(acc2[i][0]);
        float2 f1 = unpk2(acc2[i][1]);
        float4 o;
        o.x = f0.x * inv;
        o.y = f0.y * inv;
        o.z = f1.x * inv;
        o.w = f1.y * inv;
        *(float4*)&out[((size_t)(b * Nn + qt * 128 + m)) * Cc + h * 64 + tx * 4] = o;
    }
}

extern "C" void kernel_launch(void* const* d_in, const int* in_sizes, int n_in,
                              void* d_out, int out_size)
{
    const float* x      = (const float*)d_in[0];
    const float* cosT   = (const float*)d_in[1];
    const float* sinT   = (const float*)d_in[2];
    const float* qkv_w  = (const float*)d_in[3];
    const float* qkv_b  = (const float*)d_in[4];
    const float* proj_w = (const float*)d_in[5];
    const float* proj_b = (const float*)d_in[6];
    const float* qn_w   = (const float*)d_in[7];
    const float* kn_w   = (const float*)d_in[8];
    float* out = (float*)d_out;

    float *qkv, *attn;
    __nv_bfloat16 *xe, *ae, *we1, *we2;
    cudaGetSymbolAddress((void**)&qkv, g_qkv);
    cudaGetSymbolAddress((void**)&attn, g_attn);
    cudaGetSymbolAddress((void**)&xe, g_xe);
    cudaGetSymbolAddress((void**)&ae, g_ae);
    cudaGetSymbolAddress((void**)&we1, g_we1);
    cudaGetSymbolAddress((void**)&we2, g_we2);

    cudaFuncSetAttribute(gemm_mma, cudaFuncAttributeMaxDynamicSharedMemorySize, GEMM_SMEM);

    // 1) split-expand x and qkv_w
    {
        int n2 = Mrows * Cc / 2;
        expand_act<<<(n2 + 255) / 256, 256>>>(x, xe, n2, Cc);
        int n4 = Cc * (3 * Cc) / 4;
        expand_w<<<(n4 + 255) / 256, 256>>>(qkv_w, we1, n4, 3 * Cc);
    }

    // 2) QKV GEMM (bf16x3 mma.sync): [4096,2304] @ [2304,2304]
    {
        dim3 grid((3 * Cc) / 128, Mrows / 256);
        gemm_mma<<<grid, 256, GEMM_SMEM>>>(xe, we1, qkv_b, qkv, Mrows, 3 * Cc, K3);
    }

    // 3) RMSNorm + RoPE on q,k (in place, f32)
    {
        int warps = Bb * Nn * 2 * Hh;
        norm_rope_kernel<<<warps / 8, 256>>>(qkv, cosT, sinT, qn_w, kn_w);
    }

    // 4) Flash attention (FFMA2 + MUFU-free)
    {
        int smem = (2 * 64 * QS + 128 * VSd + 3 * 128) * (int)sizeof(float);
        cudaFuncSetAttribute(attn_kernel, cudaFuncAttributeMaxDynamicSharedMemorySize, smem);
        dim3 grid(Nn / 128, Hh, Bb);
        attn_kernel<<<grid, 256, smem>>>(qkv, attn);
    }

    // 5) expand attention output and proj_w, then proj GEMM
    {
        int n2 = Mrows * Cc / 2;
        expand_act<<<(n2 + 255) / 256, 256>>>(attn, ae, n2, Cc);
        int n4 = Cc * Cc / 4;
        expand_w<<<(n4 + 255) / 256, 256>>>(proj_w, we2, n4, Cc);
        dim3 grid(Cc / 128, Mrows / 256);
        gemm_mma<<<grid, 256, GEMM_SMEM>>>(ae, we2, proj_b, out, Mrows, Cc, K3);
    }
}

// round 8
// speedup vs baseline: 1.4168x; 1.0658x over previous
#include <cuda_runtime.h>
#include <cuda_bf16.h>
#include <cuda_fp16.h>
#include <math.h>
#include <stdint.h>

#define Bb 2
#define Nn 2048
#define Cc 768
#define Hh 12
#define Dh 64
#define Mrows (Bb * Nn)   // 4096
#define K2 (2 * Cc)       // 1536 (2-term fp16 expanded K)

// Scratch (no cudaMalloc allowed)
__device__ float g_qkv[(size_t)Bb * Nn * 3 * Cc];        // [B,N,3,H,Dh] f32
__device__ float g_attn[(size_t)Bb * Nn * Cc];           // [B,N,C] f32
__device__ __half g_xe[(size_t)Mrows * K2];              // x expanded (hi,lo)
__device__ __half g_ae[(size_t)Mrows * K2];              // attn-out expanded
__device__ __half g_we1[(size_t)K2 * 3 * Cc];            // qkv_w*256 hi, rows duplicated
__device__ __half g_we2[(size_t)K2 * Cc];                // proj_w*256 hi, rows duplicated

#define WSCALE 256.0f
#define WISCALE (1.0f / 256.0f)

// ---------------------------------------------------------------------------
// Fast exp (no MUFU): exp(x) for x <= 0. FMA/ALU only.
// ---------------------------------------------------------------------------
__device__ __forceinline__ float fexp(float x) {
    float t = x * 1.442695041f;
    t = fmaxf(t, -126.0f);
    float r = t + 12582912.0f;
    int   ii = __float_as_int(r) - 0x4B400000;
    float f = t - (r - 12582912.0f);
    float p = 1.3333558e-3f;
    p = fmaf(p, f, 9.6181291e-3f);
    p = fmaf(p, f, 5.5504109e-2f);
    p = fmaf(p, f, 2.4022651e-1f);
    p = fmaf(p, f, 6.9314718e-1f);
    p = fmaf(p, f, 1.0f);
    return __int_as_float(__float_as_int(p) + (ii << 23));
}

// ---------------------------------------------------------------------------
// Packed f32x2 helpers (FFMA2 path — only reachable via PTX)
// ---------------------------------------------------------------------------
typedef unsigned long long ull;
__device__ __forceinline__ ull dup2(float x) {
    ull r;
    asm("mov.b64 %0, {%1, %1};" : "=l"(r) : "f"(x));
    return r;
}
__device__ __forceinline__ void fma2(ull& d, ull a, ull b) {
    asm("fma.rn.f32x2 %0, %1, %2, %0;" : "+l"(d) : "l"(a), "l"(b));
}
__device__ __forceinline__ void mul2(ull& d, ull a) {
    asm("mul.rn.f32x2 %0, %0, %1;" : "+l"(d) : "l"(a));
}
__device__ __forceinline__ float2 unpk2(ull v) {
    float2 f;
    asm("mov.b64 {%0, %1}, %2;" : "=f"(f.x), "=f"(f.y) : "l"(v));
    return f;
}

// ---------------------------------------------------------------------------
// MMA / LDSM / cp.async helpers
// ---------------------------------------------------------------------------
__device__ __forceinline__ void ldsm4(uint32_t* r, uint32_t addr) {
    asm volatile("ldmatrix.sync.aligned.m8n8.x4.shared.b16 {%0,%1,%2,%3}, [%4];"
                 : "=r"(r[0]), "=r"(r[1]), "=r"(r[2]), "=r"(r[3]) : "r"(addr));
}
__device__ __forceinline__ void ldsm4t(uint32_t* r, uint32_t addr) {
    asm volatile("ldmatrix.sync.aligned.m8n8.x4.trans.shared.b16 {%0,%1,%2,%3}, [%4];"
                 : "=r"(r[0]), "=r"(r[1]), "=r"(r[2]), "=r"(r[3]) : "r"(addr));
}
__device__ __forceinline__ void mma16816(float* c, const uint32_t* a,
                                         uint32_t b0, uint32_t b1) {
    asm volatile(
        "mma.sync.aligned.m16n8k16.row.col.f32.f16.f16.f32 "
        "{%0,%1,%2,%3}, {%4,%5,%6,%7}, {%8,%9}, {%0,%1,%2,%3};"
        : "+f"(c[0]), "+f"(c[1]), "+f"(c[2]), "+f"(c[3])
        : "r"(a[0]), "r"(a[1]), "r"(a[2]), "r"(a[3]), "r"(b0), "r"(b1));
}
__device__ __forceinline__ void cpa16(uint32_t dst, const void* src) {
    asm volatile("cp.async.cg.shared.global [%0], [%1], 16;" :: "r"(dst), "l"(src));
}
#define CP_COMMIT() asm volatile("cp.async.commit_group;" ::: "memory")
#define CP_WAIT(n)  asm volatile("cp.async.wait_group %0;" :: "n"(n) : "memory")

// ---------------------------------------------------------------------------
// Split-expansion kernels (2-term fp16).
// Activations: X[M,K] f32 -> Xe[M,2K] fp16, per k: (hi, lo)
// ---------------------------------------------------------------------------
__global__ __launch_bounds__(256) void expand_act(
    const float* __restrict__ X, __half* __restrict__ Xe, int MK2, int K)
{
    int idx = blockIdx.x * 256 + threadIdx.x;
    if (idx >= MK2) return;
    int Kh = K >> 1;
    int m = idx / Kh;
    int kk = idx - m * Kh;
    float2 v = *(const float2*)(X + (size_t)m * K + 2 * kk);
    __half h0 = __float2half_rn(v.x);
    __half l0 = __float2half_rn(v.x - __half2float(h0));
    __half h1 = __float2half_rn(v.y);
    __half l1 = __float2half_rn(v.y - __half2float(h1));
    __half2* o2 = (__half2*)(Xe + (size_t)m * 2 * K + 4 * kk);
    o2[0] = __halves2half2(h0, l0);
    o2[1] = __halves2half2(h1, l1);
}

// Weights: W[K,N] f32 -> We[2K,N] fp16 of (w*256) hi, rows 2k and 2k+1 identical
__global__ __launch_bounds__(256) void expand_w(
    const float* __restrict__ W, __half* __restrict__ We, int KN4, int N)
{
    int idx = blockIdx.x * 256 + threadIdx.x;
    if (idx >= KN4) return;
    int N4 = N >> 2;
    int k = idx / N4;
    int nn = (idx - k * N4) * 4;
    float4 w = *(const float4*)(W + (size_t)k * N + nn);
    __half2 hA = __halves2half2(__float2half_rn(w.x * WSCALE), __float2half_rn(w.y * WSCALE));
    __half2 hB = __halves2half2(__float2half_rn(w.z * WSCALE), __float2half_rn(w.w * WSCALE));
    size_t r = (size_t)(2 * k) * N + nn;
    *(__half2*)(We + r)     = hA;  *(__half2*)(We + r + 2)     = hB;
    *(__half2*)(We + r + N) = hA;  *(__half2*)(We + r + N + 2) = hB;
}

// ---------------------------------------------------------------------------
// fp16 tensor-core GEMM (mma.sync): C[M,N] = (Xe[M,K2] @ We[K2,N]) / 256 + bias
// CTA tile 256x128, BK=32, 8 warps (4m x 2n), warp tile 64x64,
// 3-stage cp.async pipeline.
// ---------------------------------------------------------------------------
#define PIPE 3
#define GAS 40                     // A smem row stride (elts)
#define GBS 136                    // B smem row stride (elts)
#define GA_SZ (256 * GAS)          // elts per stage
#define GB_SZ (32 * GBS)
#define STG_SZ (GA_SZ + GB_SZ)     // 14592 elts
#define GEMM_SMEM (PIPE * STG_SZ * 2)  // 87552 B

__global__ __launch_bounds__(256, 1) void gemm_mma(
    const __half* __restrict__ Ae, const __half* __restrict__ Be,
    const float* __restrict__ bias, float* __restrict__ C,
    int M, int N, int Kt)
{
    extern __shared__ __half gsm[];
    const int tid = threadIdx.x;
    const int lane = tid & 31;
    const int wid = tid >> 5;
    const int wm = wid >> 1;        // 0..3 (64 rows each)
    const int wn = wid & 1;         // 0..1 (64 cols each)
    const int m0 = blockIdx.y * 256;
    const int n0 = blockIdx.x * 128;

    const uint32_t smb = (uint32_t)__cvta_generic_to_shared(gsm);
    const int lrow = lane & 15;
    const int lsel = lane >> 4;

    const int a_row = tid >> 2, a_u = tid & 3;
    const int b_row = tid >> 4, b_u = tid & 15;

    auto load_chunk = [&](int kt, int buf) {
        uint32_t sa = smb + buf * (STG_SZ * 2);
        const __half* Agk = Ae + (size_t)m0 * Kt + kt * 32;
#pragma unroll
        for (int i = 0; i < 4; i++) {
            int row = a_row + i * 64;
            cpa16(sa + (row * GAS + a_u * 8) * 2,
                  Agk + (size_t)row * Kt + a_u * 8);
        }
        uint32_t sb = sa + GA_SZ * 2;
        const __half* Bgk = Be + (size_t)(kt * 32) * N + n0;
#pragma unroll
        for (int i = 0; i < 2; i++) {
            int row = b_row + i * 16;
            cpa16(sb + (row * GBS + b_u * 8) * 2,
                  Bgk + (size_t)row * N + b_u * 8);
        }
    };

    const int NT = Kt / 32;

#pragma unroll
    for (int s = 0; s < PIPE - 1; s++) { load_chunk(s, s); CP_COMMIT(); }

    float acc[4][8][4] = {};

    for (int kt = 0; kt < NT; kt++) {
        CP_WAIT(PIPE - 2);
        __syncthreads();

        if (kt + PIPE - 1 < NT) {
            load_chunk(kt + PIPE - 1, (kt + PIPE - 1) % PIPE);
        }
        CP_COMMIT();

        const int buf = kt % PIPE;
        const uint32_t aw = smb + buf * (STG_SZ * 2)
                          + 2 * ((wm * 64 + lrow) * GAS + lsel * 8);
        const uint32_t bw = smb + buf * (STG_SZ * 2) + GA_SZ * 2
                          + 2 * (lrow * GBS + wn * 64 + lsel * 8);
#pragma unroll
        for (int ks = 0; ks < 2; ks++) {
            uint32_t af[4][4];
#pragma unroll
            for (int mf = 0; mf < 4; mf++)
                ldsm4(af[mf], aw + 2 * (mf * 16 * GAS + ks * 16));
            uint32_t bfr[4][4];
#pragma unroll
            for (int nc = 0; nc < 4; nc++)
                ldsm4t(bfr[nc], bw + 2 * (ks * 16 * GBS + nc * 16));
#pragma unroll
            for (int mf = 0; mf < 4; mf++)
#pragma unroll
                for (int nf = 0; nf < 8; nf++)
                    mma16816(acc[mf][nf], af[mf],
                             bfr[nf >> 1][(nf & 1) * 2],
                             bfr[nf >> 1][(nf & 1) * 2 + 1]);
        }
        __syncthreads();
    }

    // epilogue: undo weight scaling, add bias
#pragma unroll
    for (int nf = 0; nf < 8; nf++) {
        int n = n0 + wn * 64 + nf * 8 + (lane & 3) * 2;
        float2 bv = *(const float2*)&bias[n];
#pragma unroll
        for (int mf = 0; mf < 4; mf++) {
            int m = m0 + wm * 64 + mf * 16 + (lane >> 2);
            float2 o0 = {fmaf(acc[mf][nf][0], WISCALE, bv.x),
                         fmaf(acc[mf][nf][1], WISCALE, bv.y)};
            float2 o1 = {fmaf(acc[mf][nf][2], WISCALE, bv.x),
                         fmaf(acc[mf][nf][3], WISCALE, bv.y)};
            *(float2*)&C[(size_t)m * N + n]       = o0;
            *(float2*)&C[(size_t)(m + 8) * N + n] = o1;
        }
    }
}

// ---------------------------------------------------------------------------
// Fused RMSNorm + RoPE for q and k, in-place on g_qkv. One warp per row.
// ---------------------------------------------------------------------------
__global__ __launch_bounds__(256) void norm_rope_kernel(
    float* __restrict__ qkv, const float* __restrict__ cosT,
    const float* __restrict__ sinT, const float* __restrict__ qn_w,
    const float* __restrict__ kn_w)
{
    int warp = (blockIdx.x * blockDim.x + threadIdx.x) >> 5;
    int lane = threadIdx.x & 31;

    int h = warp % Hh;
    int t = warp / Hh;
    int s = t & 1;
    t >>= 1;
    int n = t % Nn;
    int b = t / Nn;

    size_t base = ((((size_t)(b * Nn + n)) * 3 + s) * Hh + h) * Dh;
    float t0 = qkv[base + 2 * lane];
    float t1 = qkv[base + 2 * lane + 1];

    float ss = t0 * t0 + t1 * t1;
#pragma unroll
    for (int o = 16; o; o >>= 1) ss += __shfl_xor_sync(0xffffffffu, ss, o);
    float inv = rsqrtf(ss * (1.0f / (float)Dh) + 1e-6f);

    const float* w = s ? kn_w : qn_w;
    float x0 = t0 * inv * w[2 * lane];
    float x1 = t1 * inv * w[2 * lane + 1];

    float c = cosT[(size_t)n * (Dh / 2) + lane];
    float sn = sinT[(size_t)n * (Dh / 2) + lane];

    qkv[base + 2 * lane]     = x0 * c - x1 * sn;
    qkv[base + 2 * lane + 1] = x0 * sn + x1 * c;
}

// ---------------------------------------------------------------------------
// Flash attention (fp32 SIMT, FFMA2-packed inner GEMMs, MUFU-free softmax).
// ---------------------------------------------------------------------------
#define QS 132
#define VSd 68

__global__ __launch_bounds__(256) void attn_kernel(
    const float* __restrict__ qkv, float* __restrict__ out)
{
    extern __shared__ float smf[];
    float* Qt  = smf;
    float* KPt = Qt + 64 * QS;
    float* Vs  = KPt + 64 * QS;
    float* row_max   = Vs + 128 * VSd;
    float* row_sum   = row_max + 128;
    float* row_alpha = row_sum + 128;

    const int qt = blockIdx.x;
    const int h  = blockIdx.y;
    const int b  = blockIdx.z;
    const int tid = threadIdx.x;
    const int tx = tid & 15;
    const int ty = tid >> 4;
    const float scale = 0.125f;

    int rowi[8];
#pragma unroll
    for (int i = 0; i < 8; i++) rowi[i] = ty * 4 + (i < 4 ? i : 60 + i);

    {
        int r  = tid >> 1;
        int c0 = (tid & 1) * 32;
        size_t base = ((((size_t)(b * Nn + qt * 128 + r)) * 3 + 0) * Hh + h) * (size_t)Dh + c0;
#pragma unroll
        for (int u = 0; u < 32; u += 4) {
            float4 v = *(const float4*)&qkv[base + u];
            Qt[(c0 + u + 0) * QS + r] = v.x;
            Qt[(c0 + u + 1) * QS + r] = v.y;
            Qt[(c0 + u + 2) * QS + r] = v.z;
            Qt[(c0 + u + 3) * QS + r] = v.w;
        }
    }
    if (tid < 128) { row_max[tid] = -INFINITY; row_sum[tid] = 0.0f; }

    ull acc2[8][2] = {};

    for (int kt = 0; kt < Nn / 128; kt++) {
        __syncthreads();

        {
            int r  = tid >> 1;
            int c0 = (tid & 1) * 32;
            size_t kb = ((((size_t)(b * Nn + kt * 128 + r)) * 3 + 1) * Hh + h) * (size_t)Dh + c0;
            size_t vb = ((((size_t)(b * Nn + kt * 128 + r)) * 3 + 2) * Hh + h) * (size_t)Dh + c0;
#pragma unroll
            for (int u = 0; u < 32; u += 4) {
                float4 kv = *(const float4*)&qkv[kb + u];
                KPt[(c0 + u + 0) * QS + r] = kv.x;
                KPt[(c0 + u + 1) * QS + r] = kv.y;
                KPt[(c0 + u + 2) * QS + r] = kv.z;
                KPt[(c0 + u + 3) * QS + r] = kv.w;
                *(float4*)&Vs[r * VSd + c0 + u] = *(const float4*)&qkv[vb + u];
            }
        }
        __syncthreads();

        ull s2[8][4] = {};
#pragma unroll 4
        for (int d = 0; d < 64; d++) {
            float4 a0 = *(const float4*)&Qt[d * QS + ty * 4];
            float4 a1 = *(const float4*)&Qt[d * QS + ty * 4 + 64];
            ulonglong2 k0 = *(const ulonglong2*)&KPt[d * QS + tx * 4];
            ulonglong2 k1 = *(const ulonglong2*)&KPt[d * QS + tx * 4 + 64];
            ull ad[8] = {dup2(a0.x), dup2(a0.y), dup2(a0.z), dup2(a0.w),
                         dup2(a1.x), dup2(a1.y), dup2(a1.z), dup2(a1.w)};
            ull bj[4] = {k0.x, k0.y, k1.x, k1.y};
#pragma unroll
            for (int i = 0; i < 8; i++)
#pragma unroll
                for (int jp = 0; jp < 4; jp++)
                    fma2(s2[i][jp], ad[i], bj[jp]);
        }

        float s[8][8];
#pragma unroll
        for (int i = 0; i < 8; i++)
#pragma unroll
            for (int jp = 0; jp < 4; jp++) {
                float2 f = unpk2(s2[i][jp]);
                s[i][2 * jp]     = f.x;
                s[i][2 * jp + 1] = f.y;
            }

        float tmax[8];
#pragma unroll
        for (int i = 0; i < 8; i++) {
#pragma unroll
            for (int j = 0; j < 8; j++) s[i][j] *= scale;
            float m01 = fmaxf(fmaxf(s[i][0], s[i][1]), fmaxf(s[i][2], s[i][3]));
            float m23 = fmaxf(fmaxf(s[i][4], s[i][5]), fmaxf(s[i][6], s[i][7]));
            tmax[i] = fmaxf(m01, m23);
        }
#pragma unroll
        for (int o = 8; o; o >>= 1)
#pragma unroll
            for (int i = 0; i < 8; i++)
                tmax[i] = fmaxf(tmax[i], __shfl_xor_sync(0xffffffffu, tmax[i], o));

        if (tx == 0) {
#pragma unroll
            for (int i = 0; i < 8; i++) {
                int r = rowi[i];
                float mo = row_max[r];
                float mn = fmaxf(mo, tmax[i]);
                float al = fexp(mo - mn);
                row_max[r] = mn;
                row_alpha[r] = al;
                row_sum[r] *= al;
            }
        }
        __syncthreads();

        float tsum[8];
#pragma unroll
        for (int i = 0; i < 8; i++) {
            float mrow = row_max[rowi[i]];
            tsum[i] = 0.0f;
#pragma unroll
            for (int j = 0; j < 8; j++) {
                s[i][j] = fexp(s[i][j] - mrow);
                tsum[i] += s[i][j];
            }
        }
#pragma unroll
        for (int o = 8; o; o >>= 1)
#pragma unroll
            for (int i = 0; i < 8; i++)
                tsum[i] += __shfl_xor_sync(0xffffffffu, tsum[i], o);
        if (tx == 0) {
#pragma unroll
            for (int i = 0; i < 8; i++) row_sum[rowi[i]] += tsum[i];
        }
#pragma unroll
        for (int i = 0; i < 8; i++) {
            ull al = dup2(row_alpha[rowi[i]]);
            mul2(acc2[i][0], al);
            mul2(acc2[i][1], al);
        }

#pragma unroll
        for (int i = 0; i < 8; i++) {
            int m = rowi[i];
#pragma unroll
            for (int jj = 0; jj < 4; jj++) {
                int j = (jj + tx) & 3;
                KPt[(tx * 4 + j) * QS + m] = s[i][j];
            }
        }
        __syncthreads();

#pragma unroll 4
        for (int n = 0; n < 64; n++) {
            float4 p0 = *(const float4*)&KPt[n * QS + ty * 4];
            float4 p1 = *(const float4*)&KPt[n * QS + ty * 4 + 64];
            ulonglong2 vv = *(const ulonglong2*)&Vs[n * VSd + tx * 4];
            ull pd[8] = {dup2(p0.x), dup2(p0.y), dup2(p0.z), dup2(p0.w),
                         dup2(p1.x), dup2(p1.y), dup2(p1.z), dup2(p1.w)};
#pragma unroll
            for (int i = 0; i < 8; i++) {
                fma2(acc2[i][0], pd[i], vv.x);
                fma2(acc2[i][1], pd[i], vv.y);
            }
        }
        __syncthreads();

#pragma unroll
        for (int i = 0; i < 8; i++) {
            int m = rowi[i];
#pragma unroll
            for (int jj = 0; jj < 4; jj++) {
                int j = (jj + tx) & 3;
                KPt[(tx * 4 + j) * QS + m] = s[i][4 + j];
            }
        }
        __syncthreads();

#pragma unroll 4
        for (int n = 0; n < 64; n++) {
            float4 p0 = *(const float4*)&KPt[n * QS + ty * 4];
            float4 p1 = *(const float4*)&KPt[n * QS + ty * 4 + 64];
            ulonglong2 vv = *(const ulonglong2*)&Vs[(64 + n) * VSd + tx * 4];
            ull pd[8] = {dup2(p0.x), dup2(p0.y), dup2(p0.z), dup2(p0.w),
                         dup2(p1.x), dup2(p1.y), dup2(p1.z), dup2(p1.w)};
#pragma unroll
            for (int i = 0; i < 8; i++) {
                fma2(acc2[i][0], pd[i], vv.x);
                fma2(acc2[i][1], pd[i], vv.y);
            }
        }
    }

#pragma unroll
    for (int i = 0; i < 8; i++) {
        int m = rowi[i];
        float inv = 1.0f / row_sum[m];
        float2 f0 = unpk2(acc2[i][0]);
        float2 f1 = unpk2(acc2[i][1]);
        float4 o;
        o.x = f0.x * inv;
        o.y = f0.y * inv;
        o.z = f1.x * inv;
        o.w = f1.y * inv;
        *(float4*)&out[((size_t)(b * Nn + qt * 128 + m)) * Cc + h * 64 + tx * 4] = o;
    }
}

extern "C" void kernel_launch(void* const* d_in, const int* in_sizes, int n_in,
                              void* d_out, int out_size)
{
    const float* x      = (const float*)d_in[0];
    const float* cosT   = (const float*)d_in[1];
    const float* sinT   = (const float*)d_in[2];
    const float* qkv_w  = (const float*)d_in[3];
    const float* qkv_b  = (const float*)d_in[4];
    const float* proj_w = (const float*)d_in[5];
    const float* proj_b = (const float*)d_in[6];
    const float* qn_w   = (const float*)d_in[7];
    const float* kn_w   = (const float*)d_in[8];
    float* out = (float*)d_out;

    float *qkv, *attn;
    __half *xe, *ae, *we1, *we2;
    cudaGetSymbolAddress((void**)&qkv, g_qkv);
    cudaGetSymbolAddress((void**)&attn, g_attn);
    cudaGetSymbolAddress((void**)&xe, g_xe);
    cudaGetSymbolAddress((void**)&ae, g_ae);
    cudaGetSymbolAddress((void**)&we1, g_we1);
    cudaGetSymbolAddress((void**)&we2, g_we2);

    cudaFuncSetAttribute(gemm_mma, cudaFuncAttributeMaxDynamicSharedMemorySize, GEMM_SMEM);

    // 1) split-expand x and qkv_w (2-term fp16)
    {
        int n2 = Mrows * Cc / 2;
        expand_act<<<(n2 + 255) / 256, 256>>>(x, xe, n2, Cc);
        int n4 = Cc * (3 * Cc) / 4;
        expand_w<<<(n4 + 255) / 256, 256>>>(qkv_w, we1, n4, 3 * Cc);
    }

    // 2) QKV GEMM (fp16x2 mma.sync): [4096,1536] @ [1536,2304]
    {
        dim3 grid((3 * Cc) / 128, Mrows / 256);
        gemm_mma<<<grid, 256, GEMM_SMEM>>>(xe, we1, qkv_b, qkv, Mrows, 3 * Cc, K2);
    }

    // 3) RMSNorm + RoPE on q,k (in place, f32)
    {
        int warps = Bb * Nn * 2 * Hh;
        norm_rope_kernel<<<warps / 8, 256>>>(qkv, cosT, sinT, qn_w, kn_w);
    }

    // 4) Flash attention (FFMA2 + MUFU-free)
    {
        int smem = (2 * 64 * QS + 128 * VSd + 3 * 128) * (int)sizeof(float);
        cudaFuncSetAttribute(attn_kernel, cudaFuncAttributeMaxDynamicSharedMemorySize, smem);
        dim3 grid(Nn / 128, Hh, Bb);
        attn_kernel<<<grid, 256, smem>>>(qkv, attn);
    }

    // 5) expand attention output and proj_w, then proj GEMM
    {
        int n2 = Mrows * Cc / 2;
        expand_act<<<(n2 + 255) / 256, 256>>>(attn, ae, n2, Cc);
        int n4 = Cc * Cc / 4;
        expand_w<<<(n4 + 255) / 256, 256>>>(proj_w, we2, n4, Cc);
        dim3 grid(Cc / 128, Mrows / 256);
        gemm_mma<<<grid, 256, GEMM_SMEM>>>(ae, we2, proj_b, out, Mrows, Cc, K2);
    }
}